// round 7
// baseline (speedup 1.0000x reference)
#include <cuda_runtime.h>
#include <math.h>

// ---------------------------------------------------------------------------
// Problem constants
// ---------------------------------------------------------------------------
#define Bsz   32
#define Tlen  16
#define Slen  400
#define Hd    300
#define Ed    300
#define Ld    3
#define Vocab 50000
#define OOV   20
#define ROWS  (Bsz*Tlen)      // 512 (b,t) rows
#define VO    (Vocab+OOV)     // 50020
#define CATW  900             // [contexts(300) | hiddens(300) | x(300)]

// ---------------------------------------------------------------------------
// Scratch (static device globals: allocation-free per harness rules)
// ---------------------------------------------------------------------------
__device__ float g_cat[ROWS*CATW];                 // 1.84 MB
__device__ float g_hbuf[2][Ld][Bsz][Hd];           // ping-pong GRU state
__device__ float g_q[ROWS*Hd];
__device__ float g_feat[ROWS*Hd];
__device__ float g_logits[(size_t)ROWS*Vocab];     // 102.4 MB
__device__ float g_pgen[ROWS*2];
__device__ float g_attn_fallback[ROWS*Slen];
__device__ int   g_mask_u8;

// ---------------------------------------------------------------------------
// Mask dtype detection: bool stored as u8 -> bytes {1,1,1,...};
// bool widened to int32 -> bytes {1,0,0,0,...}. Only reads first 4 bytes (safe
// under either layout).
// ---------------------------------------------------------------------------
__global__ void detect_mask_kernel(const unsigned char* __restrict__ m) {
    g_mask_u8 = (m[1] | m[2] | m[3]) ? 1 : 0;
}

__global__ void init_hidden_kernel(const float* __restrict__ h0) {
    int i = blockIdx.x*blockDim.x + threadIdx.x;
    if (i < Ld*Bsz*Hd) ((float*)g_hbuf)[i] = h0[i];
}

__global__ void embed_kernel(const int* __restrict__ tokens,
                             const float* __restrict__ embed) {
    int i = blockIdx.x*blockDim.x + threadIdx.x;
    if (i < ROWS*Ed) {
        int row = i / Ed, e = i - row*Ed;
        g_cat[row*CATW + 600 + e] = embed[(size_t)tokens[row]*Ed + e];
    }
}

// ---------------------------------------------------------------------------
// GRU step (one (t,l) stage). Grid 150 blocks x 192 threads.
// Block covers 2 j-values x 3 gates x 32 batch. Activations staged in smem,
// weights read as uniform-per-warp float4 LDG (L2-resident across steps).
// ---------------------------------------------------------------------------
__global__ void __launch_bounds__(192) gru_step_kernel(
        int t, int l,
        const float* __restrict__ Wih_all, const float* __restrict__ Whh_all,
        const float* __restrict__ bih_all, const float* __restrict__ bhh_all) {
    __shared__ float sx[Bsz*101];     // pad 101: 5b+k mod 32 -> conflict-free
    __shared__ float sh[Bsz*101];
    __shared__ float gI[2][3][Bsz];
    __shared__ float gH[2][3][Bsz];

    int pb = t & 1, qb = pb ^ 1;
    const float* inp; int instr;
    if (l == 0) { inp = g_cat + t*CATW + 600; instr = Tlen*CATW; }
    else        { inp = &g_hbuf[qb][l-1][0][0]; instr = Hd; }
    const float* hprev = &g_hbuf[pb][l][0][0];
    float*       hout  = &g_hbuf[qb][l][0][0];

    int tid = threadIdx.x;
    int b = tid & 31, g = (tid >> 5) % 3, jj = tid / 96;
    int j = blockIdx.x*2 + jj;
    int row = g*Hd + j;
    const float* wi = Wih_all + ((size_t)l*3*Hd + row)*Ed;
    const float* wh = Whh_all + ((size_t)l*3*Hd + row)*Hd;
    float accI = bih_all[l*3*Hd + row];
    float accH = bhh_all[l*3*Hd + row];

    for (int k0 = 0; k0 < Hd; k0 += 100) {
        for (int i = tid; i < Bsz*100; i += 192) {
            int bb = i / 100, kk = i - bb*100;
            sx[bb*101 + kk] = inp[bb*instr + k0 + kk];
            sh[bb*101 + kk] = hprev[bb*Hd + k0 + kk];
        }
        __syncthreads();
        const float4* wi4 = (const float4*)(wi + k0);
        const float4* wh4 = (const float4*)(wh + k0);
        #pragma unroll
        for (int k4 = 0; k4 < 25; k4++) {
            float4 a = wi4[k4], c = wh4[k4];
            int k = k4*4;
            accI += a.x*sx[b*101+k]   + a.y*sx[b*101+k+1]
                  + a.z*sx[b*101+k+2] + a.w*sx[b*101+k+3];
            accH += c.x*sh[b*101+k]   + c.y*sh[b*101+k+1]
                  + c.z*sh[b*101+k+2] + c.w*sh[b*101+k+3];
        }
        __syncthreads();
    }
    gI[jj][g][b] = accI; gH[jj][g][b] = accH;
    __syncthreads();
    if (tid < 64) {
        int bb = tid & 31, jj2 = tid >> 5;
        int j2 = blockIdx.x*2 + jj2;
        float r = 1.f/(1.f + __expf(-(gI[jj2][0][bb] + gH[jj2][0][bb])));
        float z = 1.f/(1.f + __expf(-(gI[jj2][1][bb] + gH[jj2][1][bb])));
        float n = tanhf(gI[jj2][2][bb] + r*gH[jj2][2][bb]);
        float h = (1.f - z)*n + z*hprev[bb*Hd + j2];
        hout[bb*Hd + j2] = h;
        if (l == Ld-1) g_cat[(bb*Tlen + t)*CATW + 300 + j2] = h;
    }
}

// ---------------------------------------------------------------------------
// Generic fp32 GEMM: C[m,n] = bias[n] + sum_k A[m,k] * W[n,k]
// Block tile 64x64, K-chunk 30, 256 threads, 4x4 micro-tile.
// Inner product uses packed fma.rn.f32x2 (FFMA2) -> 2 MAC/instr, same
// rounding as scalar FFMA (bit-identical accumulation order).
// A/C selected by mode so no device-symbol addresses are needed host-side.
// ---------------------------------------------------------------------------
#define MODE_Q    0
#define MODE_FEAT 1
#define MODE_OUT  2

__global__ void __launch_bounds__(256) gemm_kernel(
        int mode, const float* __restrict__ W, const float* __restrict__ bias,
        int N, int K, int lda) {
    const float* A; float* C;
    if      (mode == MODE_Q)    { A = g_cat + 300; C = g_q; }
    else if (mode == MODE_FEAT) { A = g_cat;       C = g_feat; }
    else                        { A = g_feat;      C = g_logits; }

    __shared__ float As[30][64];
    __shared__ float Bs[30][64];
    int tid = threadIdx.x;
    int tx = tid & 15, ty = tid >> 4;
    int row0 = blockIdx.y*64, col0 = blockIdx.x*64;

    unsigned long long acc[4][2];
    #pragma unroll
    for (int i = 0; i < 4; i++) { acc[i][0] = 0ull; acc[i][1] = 0ull; }

    for (int k0 = 0; k0 < K; k0 += 30) {
        for (int i = tid; i < 64*30; i += 256) {
            int m = i/30, k = i - m*30;
            As[k][m] = A[(size_t)(row0+m)*lda + k0 + k];
            int col = col0 + m;
            Bs[k][m] = (col < N) ? W[(size_t)col*K + k0 + k] : 0.f;
        }
        __syncthreads();
        #pragma unroll
        for (int k = 0; k < 30; k++) {
            float4 av = *(const float4*)&As[k][ty*4];
            float4 bv = *(const float4*)&Bs[k][tx*4];
            unsigned long long b01, b23;
            asm("mov.b64 %0, {%1,%2};" : "=l"(b01) : "f"(bv.x), "f"(bv.y));
            asm("mov.b64 %0, {%1,%2};" : "=l"(b23) : "f"(bv.z), "f"(bv.w));
            float aarr[4] = {av.x, av.y, av.z, av.w};
            #pragma unroll
            for (int i = 0; i < 4; i++) {
                unsigned long long ap;
                asm("mov.b64 %0, {%1,%1};" : "=l"(ap) : "f"(aarr[i]));
                asm("fma.rn.f32x2 %0, %1, %2, %0;" : "+l"(acc[i][0]) : "l"(ap), "l"(b01));
                asm("fma.rn.f32x2 %0, %1, %2, %0;" : "+l"(acc[i][1]) : "l"(ap), "l"(b23));
            }
        }
        __syncthreads();
    }
    #pragma unroll
    for (int i = 0; i < 4; i++) {
        int row = row0 + ty*4 + i;              // M=512 always, no guard needed
        float c0,c1,c2,c3;
        asm("mov.b64 {%0,%1}, %2;" : "=f"(c0), "=f"(c1) : "l"(acc[i][0]));
        asm("mov.b64 {%0,%1}, %2;" : "=f"(c2), "=f"(c3) : "l"(acc[i][1]));
        int col = col0 + tx*4;
        float* crow = C + (size_t)row*N;
        if (col+0 < N) crow[col+0] = c0 + bias[col+0];
        if (col+1 < N) crow[col+1] = c1 + bias[col+1];
        if (col+2 < N) crow[col+2] = c2 + bias[col+2];
        if (col+3 < N) crow[col+3] = c3 + bias[col+3];
    }
}

// ---------------------------------------------------------------------------
// Attention: scores -> masked softmax -> attn_dist (output #2) -> contexts.
// One block per (b,t) row.
// ---------------------------------------------------------------------------
__global__ void __launch_bounds__(256) attn_kernel(
        const float* __restrict__ src, const void* __restrict__ maskp,
        float* __restrict__ attn_out) {
    __shared__ float sq[Hd];
    __shared__ float ss[Slen];
    __shared__ float red[8];
    int row = blockIdx.x;
    int b = row / Tlen;
    int tid = threadIdx.x, lane = tid & 31, warp = tid >> 5;

    for (int h = tid; h < Hd; h += 256) sq[h] = g_q[row*Hd + h];
    __syncthreads();

    const unsigned char* m8  = (const unsigned char*)maskp;
    const int*           m32 = (const int*)maskp;
    int useu8 = g_mask_u8;

    // scores: one warp per s
    for (int s = warp; s < Slen; s += 8) {
        const float* srow = src + ((size_t)b*Slen + s)*Hd;
        float p = 0.f;
        for (int h = lane; h < Hd; h += 32) p += sq[h]*srow[h];
        #pragma unroll
        for (int o = 16; o; o >>= 1) p += __shfl_xor_sync(0xffffffffu, p, o);
        if (lane == 0) {
            int mk = useu8 ? (int)m8[b*Slen + s] : m32[b*Slen + s];
            ss[s] = mk ? p : -1e9f;
        }
    }
    __syncthreads();

    // max
    float mv = -3.4e38f;
    for (int s = tid; s < Slen; s += 256) mv = fmaxf(mv, ss[s]);
    #pragma unroll
    for (int o = 16; o; o >>= 1) mv = fmaxf(mv, __shfl_xor_sync(0xffffffffu, mv, o));
    if (lane == 0) red[warp] = mv;
    __syncthreads();
    if (tid == 0) { float x = red[0]; for (int w = 1; w < 8; w++) x = fmaxf(x, red[w]); red[0] = x; }
    __syncthreads();
    float M = red[0];
    __syncthreads();

    // exp + sum (exps cached in ss)
    float sv = 0.f;
    for (int s = tid; s < Slen; s += 256) { float e = __expf(ss[s] - M); ss[s] = e; sv += e; }
    #pragma unroll
    for (int o = 16; o; o >>= 1) sv += __shfl_xor_sync(0xffffffffu, sv, o);
    if (lane == 0) red[warp] = sv;
    __syncthreads();
    if (tid == 0) { float x = 0.f; for (int w = 0; w < 8; w++) x += red[w]; red[0] = x; }
    __syncthreads();
    float inv = 1.f / red[0];

    for (int s = tid; s < Slen; s += 256)
        attn_out[(size_t)row*Slen + s] = ss[s]*inv;

    // contexts: thread per h, coalesced src column walk, 4-way MLP
    for (int h = tid; h < Hd; h += 256) {
        float a0=0.f, a1=0.f, a2=0.f, a3=0.f;
        const float* sp = src + (size_t)b*Slen*Hd + h;
        for (int s = 0; s < Slen; s += 4) {
            a0 += ss[s  ]*sp[(size_t)(s  )*Hd];
            a1 += ss[s+1]*sp[(size_t)(s+1)*Hd];
            a2 += ss[s+2]*sp[(size_t)(s+2)*Hd];
            a3 += ss[s+3]*sp[(size_t)(s+3)*Hd];
        }
        g_cat[row*CATW + h] = (a0+a1+a2+a3)*inv;
    }
}

// ---------------------------------------------------------------------------
// p_gen: [contexts|hiddens|x] @ pgen_W^T + b -> softmax(2). One warp per row.
// ---------------------------------------------------------------------------
__global__ void pgen_kernel(const float* __restrict__ pW,
                            const float* __restrict__ pb) {
    int wg = blockIdx.x*(blockDim.x >> 5) + (threadIdx.x >> 5);
    if (wg >= ROWS) return;
    int lane = threadIdx.x & 31;
    const float* crow = g_cat + wg*CATW;
    float a0 = 0.f, a1 = 0.f;
    for (int k = lane; k < CATW; k += 32) {
        float v = crow[k];
        a0 += v*pW[k];
        a1 += v*pW[CATW + k];
    }
    #pragma unroll
    for (int o = 16; o; o >>= 1) {
        a0 += __shfl_xor_sync(0xffffffffu, a0, o);
        a1 += __shfl_xor_sync(0xffffffffu, a1, o);
    }
    if (lane == 0) {
        float l0 = a0 + pb[0], l1 = a1 + pb[1];
        float m = fmaxf(l0, l1);
        float e0 = __expf(l0 - m), e1 = __expf(l1 - m);
        float inv = 1.f/(e0 + e1);
        g_pgen[wg*2+0] = e0*inv;
        g_pgen[wg*2+1] = e1*inv;
    }
}

// ---------------------------------------------------------------------------
// Vocab softmax scaled by p_gen[0]; writes final_dist rows incl. zeroed OOV
// columns. One block per (b,t) row; logits row (200KB) stays L2-hot between
// passes.
// ---------------------------------------------------------------------------
__global__ void __launch_bounds__(256) softmax_final_kernel(float* __restrict__ out) {
    __shared__ float red[8];
    int row = blockIdx.x;
    const float* lrow = g_logits + (size_t)row*Vocab;
    int tid = threadIdx.x, lane = tid & 31, warp = tid >> 5;

    float mv = -3.4e38f;
    for (int v = tid; v < Vocab; v += 256) mv = fmaxf(mv, lrow[v]);
    #pragma unroll
    for (int o = 16; o; o >>= 1) mv = fmaxf(mv, __shfl_xor_sync(0xffffffffu, mv, o));
    if (lane == 0) red[warp] = mv;
    __syncthreads();
    if (tid == 0) { float x = red[0]; for (int w = 1; w < 8; w++) x = fmaxf(x, red[w]); red[0] = x; }
    __syncthreads();
    float M = red[0];
    __syncthreads();

    float sv = 0.f;
    for (int v = tid; v < Vocab; v += 256) sv += __expf(lrow[v] - M);
    #pragma unroll
    for (int o = 16; o; o >>= 1) sv += __shfl_xor_sync(0xffffffffu, sv, o);
    if (lane == 0) red[warp] = sv;
    __syncthreads();
    if (tid == 0) { float x = 0.f; for (int w = 0; w < 8; w++) x += red[w]; red[0] = x; }
    __syncthreads();
    float S = red[0];

    float scale = g_pgen[row*2] / S;
    float* orow = out + (size_t)row*VO;
    for (int v = tid; v < VO; v += 256)
        orow[v] = (v < Vocab) ? scale*__expf(lrow[v] - M) : 0.f;
}

// ---------------------------------------------------------------------------
// Copy-mechanism scatter: final[b,t,src_oov[b,s]] += p_gen[1]*attn[b,t,s]
// ---------------------------------------------------------------------------
__global__ void scatter_kernel(float* __restrict__ out,
                               const int* __restrict__ src_oov,
                               const float* __restrict__ attn) {
    int row = blockIdx.x;
    int b = row / Tlen;
    float p1 = g_pgen[row*2+1];
    float* orow = out + (size_t)row*VO;
    for (int s = threadIdx.x; s < Slen; s += blockDim.x) {
        float a = attn[(size_t)row*Slen + s] * p1;
        int col = src_oov[b*Slen + s];
        atomicAdd(&orow[col], a);
    }
}

// ---------------------------------------------------------------------------
// Host launcher
// ---------------------------------------------------------------------------
extern "C" void kernel_launch(void* const* d_in, const int* in_sizes, int n_in,
                              void* d_out, int out_size) {
    int idx = 0;
    const int*   tokens  = (const int*)  d_in[idx++];
    const float* src     = (const float*)d_in[idx++];
    const void*  mask    =               d_in[idx++];
    const float* hidden0 = (const float*)d_in[idx++];
    const int*   src_oov = (const int*)  d_in[idx++];
    if (idx < n_in && in_sizes[idx] == 1) idx++;   // max_num_oov scalar (may be absent)
    const float* embed   = (const float*)d_in[idx++];
    const float* W_ih    = (const float*)d_in[idx++];
    const float* W_hh    = (const float*)d_in[idx++];
    const float* b_ih    = (const float*)d_in[idx++];
    const float* b_hh    = (const float*)d_in[idx++];
    const float* attn_W  = (const float*)d_in[idx++];
    const float* attn_b  = (const float*)d_in[idx++];
    const float* fc_W    = (const float*)d_in[idx++];
    const float* fc_b    = (const float*)d_in[idx++];
    const float* out_W   = (const float*)d_in[idx++];
    const float* out_b   = (const float*)d_in[idx++];
    const float* pgen_W  = (const float*)d_in[idx++];
    const float* pgen_b  = (const float*)d_in[idx++];

    float* out = (float*)d_out;
    float* attn_out;
    if (out_size >= (int)((size_t)ROWS*VO + (size_t)ROWS*Slen)) {
        attn_out = out + (size_t)ROWS*VO;          // [final_dist | attn_dist]
    } else {                                       // defensive fallback
        void* p = nullptr;
        cudaGetSymbolAddress(&p, g_attn_fallback);
        attn_out = (float*)p;
    }

    detect_mask_kernel<<<1,1>>>((const unsigned char*)mask);
    init_hidden_kernel<<<(Ld*Bsz*Hd+255)/256,256>>>(hidden0);
    embed_kernel<<<(ROWS*Ed+255)/256,256>>>(tokens, embed);

    for (int t = 0; t < Tlen; t++)
        for (int l = 0; l < Ld; l++)
            gru_step_kernel<<<150,192>>>(t, l, W_ih, W_hh, b_ih, b_hh);

    gemm_kernel<<<dim3(5,8),256>>>(MODE_Q, attn_W, attn_b, Hd, Hd, CATW);
    attn_kernel<<<ROWS,256>>>(src, mask, attn_out);
    gemm_kernel<<<dim3(5,8),256>>>(MODE_FEAT, fc_W, fc_b, Hd, 2*Hd, CATW);
    gemm_kernel<<<dim3((Vocab+63)/64,8),256>>>(MODE_OUT, out_W, out_b, Vocab, Hd, Hd);
    pgen_kernel<<<64,256>>>(pgen_W, pgen_b);
    softmax_final_kernel<<<ROWS,256>>>(out);
    scatter_kernel<<<ROWS,256>>>(out, src_oov, attn_out);
}

// round 8
// speedup vs baseline: 1.3090x; 1.3090x over previous
#include <cuda_runtime.h>
#include <math.h>

// ---------------------------------------------------------------------------
// Problem constants
// ---------------------------------------------------------------------------
#define Bsz   32
#define Tlen  16
#define Slen  400
#define Hd    300
#define Ed    300
#define Ld    3
#define Vocab 50000
#define OOV   20
#define ROWS  (Bsz*Tlen)      // 512 (b,t) rows
#define VO    (Vocab+OOV)     // 50020
#define CATW  900             // [contexts(300) | hiddens(300) | x(300)]

// Persistent GRU config
#define NBLK  100             // <= 148 SMs, 1 block/SM -> co-residency guaranteed
#define NTHR  288             // 9 warps, 18 dot-tasks -> 2 tasks/warp exactly
#define NJ    3               // j's per block: 100*3 = 300 exact
#define PADB  33              // transposed activation row pad (conflict-free)

// smem layout (floats)
#define SW_FLOATS   16200     // 3 layers * 18 tasks * 300
#define SX_OFF      16200
#define SH_OFF      (16200+9900)
#define SACC_OFF    (16200+19800)
#define SMEM_FLOATS (16200+19800+576)          // 36576
#define SMEM_BYTES  (SMEM_FLOATS*4)            // 146304 B

// ---------------------------------------------------------------------------
// Scratch (static device globals: allocation-free per harness rules)
// ---------------------------------------------------------------------------
__device__ float g_cat[ROWS*CATW];                 // 1.84 MB
__device__ float g_hall[Ld][Tlen+1][Bsz][Hd];      // h history; [l][0] = hidden0
__device__ float g_q[ROWS*Hd];
__device__ float g_feat[ROWS*Hd];
__device__ float g_logits[(size_t)ROWS*Vocab];     // 102.4 MB
__device__ float g_pgen[ROWS*2];
__device__ float g_attn_fallback[ROWS*Slen];
__device__ int   g_mask_u8;

// software grid barrier state
__device__ unsigned g_bar_cnt = 0;
__device__ unsigned g_bar_gen = 0;

// ---------------------------------------------------------------------------
__global__ void detect_mask_kernel(const unsigned char* __restrict__ m) {
    g_mask_u8 = (m[1] | m[2] | m[3]) ? 1 : 0;
}

__global__ void init_hall_kernel(const float* __restrict__ h0) {
    int i = blockIdx.x*blockDim.x + threadIdx.x;
    if (i < Ld*Bsz*Hd) {
        int l = i / (Bsz*Hd), r = i - l*(Bsz*Hd);
        (&g_hall[l][0][0][0])[r] = h0[i];
    }
}

__global__ void embed_kernel(const int* __restrict__ tokens,
                             const float* __restrict__ embed) {
    int i = blockIdx.x*blockDim.x + threadIdx.x;
    if (i < ROWS*Ed) {
        int row = i / Ed, e = i - row*Ed;
        g_cat[row*CATW + 600 + e] = embed[(size_t)tokens[row]*Ed + e];
    }
}

// ---------------------------------------------------------------------------
// Grid barrier: fence -> arrive -> last resets count, fence, bumps generation;
// others spin on generation (volatile L2 read + nanosleep backoff).
// ---------------------------------------------------------------------------
__device__ __forceinline__ void grid_barrier() {
    __threadfence();           // publish this thread's writes (all threads)
    __syncthreads();
    if (threadIdx.x == 0) {
        unsigned gen = *(volatile unsigned*)&g_bar_gen;
        if (atomicAdd(&g_bar_cnt, 1u) == NBLK - 1u) {
            atomicExch(&g_bar_cnt, 0u);
            __threadfence();
            atomicAdd(&g_bar_gen, 1u);     // release
        } else {
            while (*(volatile unsigned*)&g_bar_gen == gen) __nanosleep(64);
        }
        __threadfence();       // acquire
    }
    __syncthreads();
}

// ---------------------------------------------------------------------------
// Persistent GRU: one kernel, 18 diagonal wavefronts over the (l,t) DAG.
// Block owns j's [j0, j0+3) for all layers; weight slices live in smem for
// the whole kernel. Per cell: stage x/h transposed into smem, 9 warps do the
// 18 gate-row dot products (lane = batch), combine gates, write h to g_hall.
//
// Task id: m*9 + g*3 + jl   (m: 0=ih 1=hh; g: 0=r 1=z 2=n; jl: 0..2)
// ---------------------------------------------------------------------------
extern __shared__ float s_dyn[];

__global__ void __launch_bounds__(NTHR) gru_persistent_kernel(
        const float* __restrict__ W_ih, const float* __restrict__ W_hh,
        const float* __restrict__ b_ih, const float* __restrict__ b_hh) {
    float* sw   = s_dyn;
    float* sx   = s_dyn + SX_OFF;
    float* sh   = s_dyn + SH_OFF;
    float* sacc = s_dyn + SACC_OFF;

    const int tid = threadIdx.x;
    const int j0  = blockIdx.x * NJ;
    const int lane = tid & 31, w = tid >> 5;

    // Load this block's weight slices (all 3 layers) into smem once.
    for (int idx = tid; idx < SW_FLOATS; idx += NTHR) {
        int l = idx / 5400, r = idx - l*5400;
        int task = r / 300, k = r - task*300;
        int m = task / 9, t2 = task - m*9;
        int g = t2 / 3, jl = t2 - g*3;
        int row = g*300 + j0 + jl;
        const float* src = (m == 0) ? W_ih : W_hh;
        sw[idx] = src[(size_t)l*270000 + (size_t)row*300 + k];
    }

    for (int wf = 0; wf < Tlen + Ld - 1; wf++) {
        int lmin = wf - (Tlen-1); if (lmin < 0) lmin = 0;
        int lmax = (wf < Ld-1) ? wf : Ld-1;
        for (int l = lmin; l <= lmax; l++) {
            int t = wf - l;
            const float* xsrc; int xstr;
            if (l == 0) { xsrc = g_cat + t*CATW + 600; xstr = Tlen*CATW; }
            else        { xsrc = &g_hall[l-1][t+1][0][0]; xstr = Hd; }
            const float* hsrc = &g_hall[l][t][0][0];

            __syncthreads();   // smem reuse fence (also covers weight load, 1st iter)
            // stage activations transposed: s[k*33 + b]
            for (int i = tid; i < 2400; i += NTHR) {
                int b = i / 75, k4 = (i - b*75) * 4;
                float4 xv = *(const float4*)(xsrc + (size_t)b*xstr + k4);
                float4 hv = *(const float4*)(hsrc + b*Hd + k4);
                sx[(k4+0)*PADB + b] = xv.x; sx[(k4+1)*PADB + b] = xv.y;
                sx[(k4+2)*PADB + b] = xv.z; sx[(k4+3)*PADB + b] = xv.w;
                sh[(k4+0)*PADB + b] = hv.x; sh[(k4+1)*PADB + b] = hv.y;
                sh[(k4+2)*PADB + b] = hv.z; sh[(k4+3)*PADB + b] = hv.w;
            }
            __syncthreads();

            // dots: warp w handles tasks 2w, 2w+1 (pairs share the input
            // matrix except the (8,9) pair -> activation LDS amortized 2x)
            {
                int ta = 2*w, tb = ta + 1;
                const float* wa = sw + (l*18 + ta)*300;
                const float* wb = sw + (l*18 + tb)*300;
                float acca = 0.f, accb = 0.f;
                if (ta != 8) {
                    const float* s = (ta < 9) ? sx : sh;
                    #pragma unroll 5
                    for (int k = 0; k < 300; k += 4) {
                        float4 a4 = *(const float4*)(wa + k);
                        float4 b4 = *(const float4*)(wb + k);
                        float x0 = s[(k+0)*PADB + lane];
                        float x1 = s[(k+1)*PADB + lane];
                        float x2 = s[(k+2)*PADB + lane];
                        float x3 = s[(k+3)*PADB + lane];
                        acca += a4.x*x0 + a4.y*x1 + a4.z*x2 + a4.w*x3;
                        accb += b4.x*x0 + b4.y*x1 + b4.z*x2 + b4.w*x3;
                    }
                } else {  // mixed pair: task 8 reads sx, task 9 reads sh
                    #pragma unroll 5
                    for (int k = 0; k < 300; k += 4) {
                        float4 a4 = *(const float4*)(wa + k);
                        float4 b4 = *(const float4*)(wb + k);
                        float x0 = sx[(k+0)*PADB + lane];
                        float x1 = sx[(k+1)*PADB + lane];
                        float x2 = sx[(k+2)*PADB + lane];
                        float x3 = sx[(k+3)*PADB + lane];
                        float y0 = sh[(k+0)*PADB + lane];
                        float y1 = sh[(k+1)*PADB + lane];
                        float y2 = sh[(k+2)*PADB + lane];
                        float y3 = sh[(k+3)*PADB + lane];
                        acca += a4.x*x0 + a4.y*x1 + a4.z*x2 + a4.w*x3;
                        accb += b4.x*y0 + b4.y*y1 + b4.z*y2 + b4.w*y3;
                    }
                }
                sacc[ta*32 + lane] = acca;
                sacc[tb*32 + lane] = accb;
            }
            __syncthreads();

            // gate combine: thread (b, jl) for tid < 96
            if (tid < 96) {
                int b = tid & 31, jl = tid >> 5;
                int j = j0 + jl;
                float i_r = sacc[( 0+jl)*32+b] + b_ih[l*900 +       j];
                float i_z = sacc[( 3+jl)*32+b] + b_ih[l*900 + 300 + j];
                float i_n = sacc[( 6+jl)*32+b] + b_ih[l*900 + 600 + j];
                float h_r = sacc[( 9+jl)*32+b] + b_hh[l*900 +       j];
                float h_z = sacc[(12+jl)*32+b] + b_hh[l*900 + 300 + j];
                float h_n = sacc[(15+jl)*32+b] + b_hh[l*900 + 600 + j];
                float r = 1.f/(1.f + __expf(-(i_r + h_r)));
                float z = 1.f/(1.f + __expf(-(i_z + h_z)));
                float n = tanhf(i_n + r*h_n);
                float hp = g_hall[l][t][b][j];
                float hv = (1.f - z)*n + z*hp;
                g_hall[l][t+1][b][j] = hv;
                if (l == Ld-1) g_cat[(b*Tlen + t)*CATW + 300 + j] = hv;
            }
        }
        grid_barrier();
    }
}

// ---------------------------------------------------------------------------
// Generic fp32 GEMM: C[m,n] = bias[n] + sum_k A[m,k] * W[n,k]   (unchanged)
// ---------------------------------------------------------------------------
#define MODE_Q    0
#define MODE_FEAT 1
#define MODE_OUT  2

__global__ void __launch_bounds__(256) gemm_kernel(
        int mode, const float* __restrict__ W, const float* __restrict__ bias,
        int N, int K, int lda) {
    const float* A; float* C;
    if      (mode == MODE_Q)    { A = g_cat + 300; C = g_q; }
    else if (mode == MODE_FEAT) { A = g_cat;       C = g_feat; }
    else                        { A = g_feat;      C = g_logits; }

    __shared__ float As[30][64];
    __shared__ float Bs[30][64];
    int tid = threadIdx.x;
    int tx = tid & 15, ty = tid >> 4;
    int row0 = blockIdx.y*64, col0 = blockIdx.x*64;

    unsigned long long acc[4][2];
    #pragma unroll
    for (int i = 0; i < 4; i++) { acc[i][0] = 0ull; acc[i][1] = 0ull; }

    for (int k0 = 0; k0 < K; k0 += 30) {
        for (int i = tid; i < 64*30; i += 256) {
            int m = i/30, k = i - m*30;
            As[k][m] = A[(size_t)(row0+m)*lda + k0 + k];
            int col = col0 + m;
            Bs[k][m] = (col < N) ? W[(size_t)col*K + k0 + k] : 0.f;
        }
        __syncthreads();
        #pragma unroll
        for (int k = 0; k < 30; k++) {
            float4 av = *(const float4*)&As[k][ty*4];
            float4 bv = *(const float4*)&Bs[k][tx*4];
            unsigned long long b01, b23;
            asm("mov.b64 %0, {%1,%2};" : "=l"(b01) : "f"(bv.x), "f"(bv.y));
            asm("mov.b64 %0, {%1,%2};" : "=l"(b23) : "f"(bv.z), "f"(bv.w));
            float aarr[4] = {av.x, av.y, av.z, av.w};
            #pragma unroll
            for (int i = 0; i < 4; i++) {
                unsigned long long ap;
                asm("mov.b64 %0, {%1,%1};" : "=l"(ap) : "f"(aarr[i]));
                asm("fma.rn.f32x2 %0, %1, %2, %0;" : "+l"(acc[i][0]) : "l"(ap), "l"(b01));
                asm("fma.rn.f32x2 %0, %1, %2, %0;" : "+l"(acc[i][1]) : "l"(ap), "l"(b23));
            }
        }
        __syncthreads();
    }
    #pragma unroll
    for (int i = 0; i < 4; i++) {
        int row = row0 + ty*4 + i;
        float c0,c1,c2,c3;
        asm("mov.b64 {%0,%1}, %2;" : "=f"(c0), "=f"(c1) : "l"(acc[i][0]));
        asm("mov.b64 {%0,%1}, %2;" : "=f"(c2), "=f"(c3) : "l"(acc[i][1]));
        int col = col0 + tx*4;
        float* crow = C + (size_t)row*N;
        if (col+0 < N) crow[col+0] = c0 + bias[col+0];
        if (col+1 < N) crow[col+1] = c1 + bias[col+1];
        if (col+2 < N) crow[col+2] = c2 + bias[col+2];
        if (col+3 < N) crow[col+3] = c3 + bias[col+3];
    }
}

// ---------------------------------------------------------------------------
// Attention (unchanged)
// ---------------------------------------------------------------------------
__global__ void __launch_bounds__(256) attn_kernel(
        const float* __restrict__ src, const void* __restrict__ maskp,
        float* __restrict__ attn_out) {
    __shared__ float sq[Hd];
    __shared__ float ss[Slen];
    __shared__ float red[8];
    int row = blockIdx.x;
    int b = row / Tlen;
    int tid = threadIdx.x, lane = tid & 31, warp = tid >> 5;

    for (int h = tid; h < Hd; h += 256) sq[h] = g_q[row*Hd + h];
    __syncthreads();

    const unsigned char* m8  = (const unsigned char*)maskp;
    const int*           m32 = (const int*)maskp;
    int useu8 = g_mask_u8;

    for (int s = warp; s < Slen; s += 8) {
        const float* srow = src + ((size_t)b*Slen + s)*Hd;
        float p = 0.f;
        for (int h = lane; h < Hd; h += 32) p += sq[h]*srow[h];
        #pragma unroll
        for (int o = 16; o; o >>= 1) p += __shfl_xor_sync(0xffffffffu, p, o);
        if (lane == 0) {
            int mk = useu8 ? (int)m8[b*Slen + s] : m32[b*Slen + s];
            ss[s] = mk ? p : -1e9f;
        }
    }
    __syncthreads();

    float mv = -3.4e38f;
    for (int s = tid; s < Slen; s += 256) mv = fmaxf(mv, ss[s]);
    #pragma unroll
    for (int o = 16; o; o >>= 1) mv = fmaxf(mv, __shfl_xor_sync(0xffffffffu, mv, o));
    if (lane == 0) red[warp] = mv;
    __syncthreads();
    if (tid == 0) { float x = red[0]; for (int w = 1; w < 8; w++) x = fmaxf(x, red[w]); red[0] = x; }
    __syncthreads();
    float M = red[0];
    __syncthreads();

    float sv = 0.f;
    for (int s = tid; s < Slen; s += 256) { float e = __expf(ss[s] - M); ss[s] = e; sv += e; }
    #pragma unroll
    for (int o = 16; o; o >>= 1) sv += __shfl_xor_sync(0xffffffffu, sv, o);
    if (lane == 0) red[warp] = sv;
    __syncthreads();
    if (tid == 0) { float x = 0.f; for (int w = 0; w < 8; w++) x += red[w]; red[0] = x; }
    __syncthreads();
    float inv = 1.f / red[0];

    for (int s = tid; s < Slen; s += 256)
        attn_out[(size_t)row*Slen + s] = ss[s]*inv;

    for (int h = tid; h < Hd; h += 256) {
        float a0=0.f, a1=0.f, a2=0.f, a3=0.f;
        const float* sp = src + (size_t)b*Slen*Hd + h;
        for (int s = 0; s < Slen; s += 4) {
            a0 += ss[s  ]*sp[(size_t)(s  )*Hd];
            a1 += ss[s+1]*sp[(size_t)(s+1)*Hd];
            a2 += ss[s+2]*sp[(size_t)(s+2)*Hd];
            a3 += ss[s+3]*sp[(size_t)(s+3)*Hd];
        }
        g_cat[row*CATW + h] = (a0+a1+a2+a3)*inv;
    }
}

// ---------------------------------------------------------------------------
// p_gen (unchanged)
// ---------------------------------------------------------------------------
__global__ void pgen_kernel(const float* __restrict__ pW,
                            const float* __restrict__ pb) {
    int wg = blockIdx.x*(blockDim.x >> 5) + (threadIdx.x >> 5);
    if (wg >= ROWS) return;
    int lane = threadIdx.x & 31;
    const float* crow = g_cat + wg*CATW;
    float a0 = 0.f, a1 = 0.f;
    for (int k = lane; k < CATW; k += 32) {
        float v = crow[k];
        a0 += v*pW[k];
        a1 += v*pW[CATW + k];
    }
    #pragma unroll
    for (int o = 16; o; o >>= 1) {
        a0 += __shfl_xor_sync(0xffffffffu, a0, o);
        a1 += __shfl_xor_sync(0xffffffffu, a1, o);
    }
    if (lane == 0) {
        float l0 = a0 + pb[0], l1 = a1 + pb[1];
        float m = fmaxf(l0, l1);
        float e0 = __expf(l0 - m), e1 = __expf(l1 - m);
        float inv = 1.f/(e0 + e1);
        g_pgen[wg*2+0] = e0*inv;
        g_pgen[wg*2+1] = e1*inv;
    }
}

// ---------------------------------------------------------------------------
// Vocab softmax + final dist (unchanged)
// ---------------------------------------------------------------------------
__global__ void __launch_bounds__(256) softmax_final_kernel(float* __restrict__ out) {
    __shared__ float red[8];
    int row = blockIdx.x;
    const float* lrow = g_logits + (size_t)row*Vocab;
    int tid = threadIdx.x, lane = tid & 31, warp = tid >> 5;

    float mv = -3.4e38f;
    for (int v = tid; v < Vocab; v += 256) mv = fmaxf(mv, lrow[v]);
    #pragma unroll
    for (int o = 16; o; o >>= 1) mv = fmaxf(mv, __shfl_xor_sync(0xffffffffu, mv, o));
    if (lane == 0) red[warp] = mv;
    __syncthreads();
    if (tid == 0) { float x = red[0]; for (int w = 1; w < 8; w++) x = fmaxf(x, red[w]); red[0] = x; }
    __syncthreads();
    float M = red[0];
    __syncthreads();

    float sv = 0.f;
    for (int v = tid; v < Vocab; v += 256) sv += __expf(lrow[v] - M);
    #pragma unroll
    for (int o = 16; o; o >>= 1) sv += __shfl_xor_sync(0xffffffffu, sv, o);
    if (lane == 0) red[warp] = sv;
    __syncthreads();
    if (tid == 0) { float x = 0.f; for (int w = 0; w < 8; w++) x += red[w]; red[0] = x; }
    __syncthreads();
    float S = red[0];

    float scale = g_pgen[row*2] / S;
    float* orow = out + (size_t)row*VO;
    for (int v = tid; v < VO; v += 256)
        orow[v] = (v < Vocab) ? scale*__expf(lrow[v] - M) : 0.f;
}

// ---------------------------------------------------------------------------
// Copy-mechanism scatter (unchanged)
// ---------------------------------------------------------------------------
__global__ void scatter_kernel(float* __restrict__ out,
                               const int* __restrict__ src_oov,
                               const float* __restrict__ attn) {
    int row = blockIdx.x;
    int b = row / Tlen;
    float p1 = g_pgen[row*2+1];
    float* orow = out + (size_t)row*VO;
    for (int s = threadIdx.x; s < Slen; s += blockDim.x) {
        float a = attn[(size_t)row*Slen + s] * p1;
        int col = src_oov[b*Slen + s];
        atomicAdd(&orow[col], a);
    }
}

// ---------------------------------------------------------------------------
// Host launcher
// ---------------------------------------------------------------------------
extern "C" void kernel_launch(void* const* d_in, const int* in_sizes, int n_in,
                              void* d_out, int out_size) {
    int idx = 0;
    const int*   tokens  = (const int*)  d_in[idx++];
    const float* src     = (const float*)d_in[idx++];
    const void*  mask    =               d_in[idx++];
    const float* hidden0 = (const float*)d_in[idx++];
    const int*   src_oov = (const int*)  d_in[idx++];
    if (idx < n_in && in_sizes[idx] == 1) idx++;   // max_num_oov scalar (may be absent)
    const float* embed   = (const float*)d_in[idx++];
    const float* W_ih    = (const float*)d_in[idx++];
    const float* W_hh    = (const float*)d_in[idx++];
    const float* b_ih    = (const float*)d_in[idx++];
    const float* b_hh    = (const float*)d_in[idx++];
    const float* attn_W  = (const float*)d_in[idx++];
    const float* attn_b  = (const float*)d_in[idx++];
    const float* fc_W    = (const float*)d_in[idx++];
    const float* fc_b    = (const float*)d_in[idx++];
    const float* out_W   = (const float*)d_in[idx++];
    const float* out_b   = (const float*)d_in[idx++];
    const float* pgen_W  = (const float*)d_in[idx++];
    const float* pgen_b  = (const float*)d_in[idx++];

    float* out = (float*)d_out;
    float* attn_out;
    if (out_size >= (int)((size_t)ROWS*VO + (size_t)ROWS*Slen)) {
        attn_out = out + (size_t)ROWS*VO;          // [final_dist | attn_dist]
    } else {
        void* p = nullptr;
        cudaGetSymbolAddress(&p, g_attn_fallback);
        attn_out = (float*)p;
    }

    cudaFuncSetAttribute(gru_persistent_kernel,
                         cudaFuncAttributeMaxDynamicSharedMemorySize, SMEM_BYTES);

    detect_mask_kernel<<<1,1>>>((const unsigned char*)mask);
    init_hall_kernel<<<(Ld*Bsz*Hd+255)/256,256>>>(hidden0);
    embed_kernel<<<(ROWS*Ed+255)/256,256>>>(tokens, embed);

    gru_persistent_kernel<<<NBLK, NTHR, SMEM_BYTES>>>(W_ih, W_hh, b_ih, b_hh);

    gemm_kernel<<<dim3(5,8),256>>>(MODE_Q, attn_W, attn_b, Hd, Hd, CATW);
    attn_kernel<<<ROWS,256>>>(src, mask, attn_out);
    gemm_kernel<<<dim3(5,8),256>>>(MODE_FEAT, fc_W, fc_b, Hd, 2*Hd, CATW);
    gemm_kernel<<<dim3((Vocab+63)/64,8),256>>>(MODE_OUT, out_W, out_b, Vocab, Hd, Hd);
    pgen_kernel<<<64,256>>>(pgen_W, pgen_b);
    softmax_final_kernel<<<ROWS,256>>>(out);
    scatter_kernel<<<ROWS,256>>>(out, src_oov, attn_out);
}

// round 9
// speedup vs baseline: 1.9666x; 1.5024x over previous
#include <cuda_runtime.h>
#include <math.h>

// ---------------------------------------------------------------------------
// Problem constants
// ---------------------------------------------------------------------------
#define Bsz   32
#define Tlen  16
#define Slen  400
#define Hd    300
#define Ed    300
#define Ld    3
#define Vocab 50000
#define OOV   20
#define ROWS  (Bsz*Tlen)      // 512 (b,t) rows
#define VO    (Vocab+OOV)     // 50020
#define CATW  900             // [contexts(300) | hiddens(300) | x(300)]

// Persistent GRU config
#define NBLK  100             // 1 block/SM -> co-residency guaranteed
#define NTHR  576             // 18 warps = 9 task-pairs x 2 k-halves
#define NJ    3               // j's per block: 100*3 = 300 exact
#define SB    302             // activation stride [b][k]: LDS.64 conflict-free

// smem layout (floats)
#define SW_FLOATS   16200     // 3 layers * 18 tasks * 300
#define SX_OFF      16200
#define SH_OFF      (SX_OFF + Bsz*SB)          // 25864
#define SACC_OFF    (SH_OFF + Bsz*SB)          // 35528
#define SMEM_FLOATS (SACC_OFF + 18*64)         // 36680
#define SMEM_BYTES  (SMEM_FLOATS*4)            // 146720 B

#define FMA2(acc, x, y) asm("fma.rn.f32x2 %0, %1, %2, %0;" : "+l"(acc) : "l"(x), "l"(y))

// ---------------------------------------------------------------------------
// Scratch (static device globals: allocation-free per harness rules)
// ---------------------------------------------------------------------------
__device__ float g_cat[ROWS*CATW];                 // 1.84 MB
__device__ float g_hall[Ld][Tlen+1][Bsz][Hd];      // h history; [l][0] = hidden0
__device__ float g_q[ROWS*Hd];
__device__ float g_feat[ROWS*Hd];
__device__ float g_logits[(size_t)ROWS*Vocab];     // 102.4 MB
__device__ float g_pgen[ROWS*2];
__device__ float g_attn_fallback[ROWS*Slen];
__device__ int   g_mask_u8;

__device__ unsigned g_bar_cnt = 0;
__device__ unsigned g_bar_gen = 0;

// ---------------------------------------------------------------------------
__global__ void detect_mask_kernel(const unsigned char* __restrict__ m) {
    g_mask_u8 = (m[1] | m[2] | m[3]) ? 1 : 0;
}

__global__ void init_hall_kernel(const float* __restrict__ h0) {
    int i = blockIdx.x*blockDim.x + threadIdx.x;
    if (i < Ld*Bsz*Hd) {
        int l = i / (Bsz*Hd), r = i - l*(Bsz*Hd);
        (&g_hall[l][0][0][0])[r] = h0[i];
    }
}

__global__ void embed_kernel(const int* __restrict__ tokens,
                             const float* __restrict__ embed) {
    int i = blockIdx.x*blockDim.x + threadIdx.x;
    if (i < ROWS*Ed) {
        int row = i / Ed, e = i - row*Ed;
        g_cat[row*CATW + 600 + e] = embed[(size_t)tokens[row]*Ed + e];
    }
}

// ---------------------------------------------------------------------------
// Grid barrier
// ---------------------------------------------------------------------------
__device__ __forceinline__ void grid_barrier() {
    __threadfence();
    __syncthreads();
    if (threadIdx.x == 0) {
        unsigned gen = *(volatile unsigned*)&g_bar_gen;
        if (atomicAdd(&g_bar_cnt, 1u) == NBLK - 1u) {
            atomicExch(&g_bar_cnt, 0u);
            __threadfence();
            atomicAdd(&g_bar_gen, 1u);
        } else {
            while (*(volatile unsigned*)&g_bar_gen == gen) __nanosleep(32);
        }
        __threadfence();
    }
    __syncthreads();
}

// ---------------------------------------------------------------------------
// Persistent GRU v3: 18 warps; warp w = (pair p = w/2, half hf = w&1).
// Pair p covers tasks (2p, 2p+1); tasks 0..8 read x, 9..17 read h, so all
// pairs except p==4 share their activation stream (LDS amortized 2x).
// Activations staged [b][k] (stride 302); weights consumed as packed f32x2
// pairs via ulonglong2 LDS; inner loop = fma.rn.f32x2, 2 packed accs/task.
// Task id: m*9 + g*3 + jl   (m: 0=ih 1=hh; g: 0=r 1=z 2=n; jl: 0..2)
// ---------------------------------------------------------------------------
extern __shared__ float s_dyn[];

__global__ void __launch_bounds__(NTHR) gru_persistent_kernel(
        const float* __restrict__ W_ih, const float* __restrict__ W_hh,
        const float* __restrict__ b_ih, const float* __restrict__ b_hh) {
    float* sw   = s_dyn;
    float* sx   = s_dyn + SX_OFF;
    float* sh   = s_dyn + SH_OFF;
    float* sacc = s_dyn + SACC_OFF;

    const int tid  = threadIdx.x;
    const int j0   = blockIdx.x * NJ;
    const int lane = tid & 31, w = tid >> 5;
    const int p = w >> 1, hf = w & 1;
    const int tA = 2*p, tB = tA + 1;
    const int kbeg = hf ? 152 : 0;
    const int kend = hf ? 300 : 152;

    // Load this block's weight slices (all 3 layers) into smem once.
    for (int idx = tid; idx < SW_FLOATS; idx += NTHR) {
        int l = idx / 5400, r = idx - l*5400;
        int task = r / 300, k = r - task*300;
        int m = task / 9, t2 = task - m*9;
        int g = t2 / 3, jl = t2 - g*3;
        int row = g*300 + j0 + jl;
        const float* src = (m == 0) ? W_ih : W_hh;
        sw[idx] = src[(size_t)l*270000 + (size_t)row*300 + k];
    }

    for (int wf = 0; wf < Tlen + Ld - 1; wf++) {
        int lmin = wf - (Tlen-1); if (lmin < 0) lmin = 0;
        int lmax = (wf < Ld-1) ? wf : Ld-1;
        for (int l = lmin; l <= lmax; l++) {
            int t = wf - l;
            const float* xsrc; int xstr;
            if (l == 0) { xsrc = g_cat + t*CATW + 600; xstr = Tlen*CATW; }
            else        { xsrc = &g_hall[l-1][t+1][0][0]; xstr = Hd; }
            const float* hsrc = &g_hall[l][t][0][0];

            __syncthreads();   // protect previous cell's act reads (and 1st-iter weight load)
            // stage activations [b][k]: float4 LDG, 2x STS.64 (conflict-free)
            for (int i = tid; i < Bsz*75; i += NTHR) {
                int b = i / 75, q4 = (i - b*75)*4;
                float4 xv = *(const float4*)(xsrc + (size_t)b*xstr + q4);
                float4 hv = *(const float4*)(hsrc + b*Hd + q4);
                *(float2*)&sx[b*SB + q4    ] = make_float2(xv.x, xv.y);
                *(float2*)&sx[b*SB + q4 + 2] = make_float2(xv.z, xv.w);
                *(float2*)&sh[b*SB + q4    ] = make_float2(hv.x, hv.y);
                *(float2*)&sh[b*SB + q4 + 2] = make_float2(hv.z, hv.w);
            }
            __syncthreads();

            // dot products
            {
                const float* wA = sw + (l*18 + tA)*300;
                const float* wB = sw + (l*18 + tB)*300;
                const float* aA = ((tA < 9) ? sx : sh) + lane*SB;
                const float* aB = ((tB < 9) ? sx : sh) + lane*SB;
                unsigned long long accA0 = 0ull, accA1 = 0ull;
                unsigned long long accB0 = 0ull, accB1 = 0ull;
                int k = kbeg;
                if (p != 4) {   // shared activation stream
                    for (; k + 8 <= kend; k += 8) {
                        ulonglong2 wa0 = *(const ulonglong2*)(wA + k);
                        ulonglong2 wa1 = *(const ulonglong2*)(wA + k + 4);
                        ulonglong2 wb0 = *(const ulonglong2*)(wB + k);
                        ulonglong2 wb1 = *(const ulonglong2*)(wB + k + 4);
                        unsigned long long x0 = *(const unsigned long long*)(aA + k);
                        unsigned long long x1 = *(const unsigned long long*)(aA + k + 2);
                        unsigned long long x2 = *(const unsigned long long*)(aA + k + 4);
                        unsigned long long x3 = *(const unsigned long long*)(aA + k + 6);
                        FMA2(accA0, wa0.x, x0); FMA2(accA1, wa0.y, x1);
                        FMA2(accB0, wb0.x, x0); FMA2(accB1, wb0.y, x1);
                        FMA2(accA0, wa1.x, x2); FMA2(accA1, wa1.y, x3);
                        FMA2(accB0, wb1.x, x2); FMA2(accB1, wb1.y, x3);
                    }
                    if (k < kend) {   // 4-float tail
                        ulonglong2 wa = *(const ulonglong2*)(wA + k);
                        ulonglong2 wb = *(const ulonglong2*)(wB + k);
                        unsigned long long x0 = *(const unsigned long long*)(aA + k);
                        unsigned long long x1 = *(const unsigned long long*)(aA + k + 2);
                        FMA2(accA0, wa.x, x0); FMA2(accA1, wa.y, x1);
                        FMA2(accB0, wb.x, x0); FMA2(accB1, wb.y, x1);
                    }
                } else {        // mixed pair (task 8 reads x, task 9 reads h)
                    for (; k + 8 <= kend; k += 8) {
                        ulonglong2 wa0 = *(const ulonglong2*)(wA + k);
                        ulonglong2 wa1 = *(const ulonglong2*)(wA + k + 4);
                        ulonglong2 wb0 = *(const ulonglong2*)(wB + k);
                        ulonglong2 wb1 = *(const ulonglong2*)(wB + k + 4);
                        unsigned long long x0 = *(const unsigned long long*)(aA + k);
                        unsigned long long x1 = *(const unsigned long long*)(aA + k + 2);
                        unsigned long long x2 = *(const unsigned long long*)(aA + k + 4);
                        unsigned long long x3 = *(const unsigned long long*)(aA + k + 6);
                        unsigned long long y0 = *(const unsigned long long*)(aB + k);
                        unsigned long long y1 = *(const unsigned long long*)(aB + k + 2);
                        unsigned long long y2 = *(const unsigned long long*)(aB + k + 4);
                        unsigned long long y3 = *(const unsigned long long*)(aB + k + 6);
                        FMA2(accA0, wa0.x, x0); FMA2(accA1, wa0.y, x1);
                        FMA2(accB0, wb0.x, y0); FMA2(accB1, wb0.y, y1);
                        FMA2(accA0, wa1.x, x2); FMA2(accA1, wa1.y, x3);
                        FMA2(accB0, wb1.x, y2); FMA2(accB1, wb1.y, y3);
                    }
                    if (k < kend) {
                        ulonglong2 wa = *(const ulonglong2*)(wA + k);
                        ulonglong2 wb = *(const ulonglong2*)(wB + k);
                        unsigned long long x0 = *(const unsigned long long*)(aA + k);
                        unsigned long long x1 = *(const unsigned long long*)(aA + k + 2);
                        unsigned long long y0 = *(const unsigned long long*)(aB + k);
                        unsigned long long y1 = *(const unsigned long long*)(aB + k + 2);
                        FMA2(accA0, wa.x, x0); FMA2(accA1, wa.y, x1);
                        FMA2(accB0, wb.x, y0); FMA2(accB1, wb.y, y1);
                    }
                }
                float a0,a1,a2,a3;
                asm("mov.b64 {%0,%1}, %2;" : "=f"(a0), "=f"(a1) : "l"(accA0));
                asm("mov.b64 {%0,%1}, %2;" : "=f"(a2), "=f"(a3) : "l"(accA1));
                sacc[tA*64 + hf*32 + lane] = (a0+a1) + (a2+a3);
                asm("mov.b64 {%0,%1}, %2;" : "=f"(a0), "=f"(a1) : "l"(accB0));
                asm("mov.b64 {%0,%1}, %2;" : "=f"(a2), "=f"(a3) : "l"(accB1));
                sacc[tB*64 + hf*32 + lane] = (a0+a1) + (a2+a3);
            }
            __syncthreads();

            // gate combine: thread (b, jl) for tid < 96; sum the two k-halves
            if (tid < 96) {
                int b = tid & 31, jl = tid >> 5;
                int j = j0 + jl;
                float i_r = sacc[( 0+jl)*64+b] + sacc[( 0+jl)*64+32+b] + b_ih[l*900 +       j];
                float i_z = sacc[( 3+jl)*64+b] + sacc[( 3+jl)*64+32+b] + b_ih[l*900 + 300 + j];
                float i_n = sacc[( 6+jl)*64+b] + sacc[( 6+jl)*64+32+b] + b_ih[l*900 + 600 + j];
                float h_r = sacc[( 9+jl)*64+b] + sacc[( 9+jl)*64+32+b] + b_hh[l*900 +       j];
                float h_z = sacc[(12+jl)*64+b] + sacc[(12+jl)*64+32+b] + b_hh[l*900 + 300 + j];
                float h_n = sacc[(15+jl)*64+b] + sacc[(15+jl)*64+32+b] + b_hh[l*900 + 600 + j];
                float r = 1.f/(1.f + __expf(-(i_r + h_r)));
                float z = 1.f/(1.f + __expf(-(i_z + h_z)));
                float n = tanhf(i_n + r*h_n);
                float hp = g_hall[l][t][b][j];
                float hv = (1.f - z)*n + z*hp;
                g_hall[l][t+1][b][j] = hv;
                if (l == Ld-1) g_cat[(b*Tlen + t)*CATW + 300 + j] = hv;
            }
        }
        grid_barrier();
    }
}

// ---------------------------------------------------------------------------
// Generic fp32 GEMM: C[m,n] = bias[n] + sum_k A[m,k] * W[n,k]
// Tiles padded to stride 68: staging STS conflicts drop ~30-way -> 4-way;
// compute float4 reads stay aligned + conflict-free.
// ---------------------------------------------------------------------------
#define MODE_Q    0
#define MODE_FEAT 1
#define MODE_OUT  2
#define TS 68

__global__ void __launch_bounds__(256) gemm_kernel(
        int mode, const float* __restrict__ W, const float* __restrict__ bias,
        int N, int K, int lda) {
    const float* A; float* C;
    if      (mode == MODE_Q)    { A = g_cat + 300; C = g_q; }
    else if (mode == MODE_FEAT) { A = g_cat;       C = g_feat; }
    else                        { A = g_feat;      C = g_logits; }

    __shared__ float As[30*TS];
    __shared__ float Bs[30*TS];
    int tid = threadIdx.x;
    int tx = tid & 15, ty = tid >> 4;
    int row0 = blockIdx.y*64, col0 = blockIdx.x*64;

    unsigned long long acc[4][2];
    #pragma unroll
    for (int i = 0; i < 4; i++) { acc[i][0] = 0ull; acc[i][1] = 0ull; }

    for (int k0 = 0; k0 < K; k0 += 30) {
        for (int i = tid; i < 64*30; i += 256) {
            int m = i/30, k = i - m*30;
            As[k*TS + m] = A[(size_t)(row0+m)*lda + k0 + k];
            int col = col0 + m;
            Bs[k*TS + m] = (col < N) ? W[(size_t)col*K + k0 + k] : 0.f;
        }
        __syncthreads();
        #pragma unroll
        for (int k = 0; k < 30; k++) {
            float4 av = *(const float4*)&As[k*TS + ty*4];
            float4 bv = *(const float4*)&Bs[k*TS + tx*4];
            unsigned long long b01, b23;
            asm("mov.b64 %0, {%1,%2};" : "=l"(b01) : "f"(bv.x), "f"(bv.y));
            asm("mov.b64 %0, {%1,%2};" : "=l"(b23) : "f"(bv.z), "f"(bv.w));
            float aarr[4] = {av.x, av.y, av.z, av.w};
            #pragma unroll
            for (int i = 0; i < 4; i++) {
                unsigned long long ap;
                asm("mov.b64 %0, {%1,%1};" : "=l"(ap) : "f"(aarr[i]));
                FMA2(acc[i][0], ap, b01);
                FMA2(acc[i][1], ap, b23);
            }
        }
        __syncthreads();
    }
    #pragma unroll
    for (int i = 0; i < 4; i++) {
        int row = row0 + ty*4 + i;
        float c0,c1,c2,c3;
        asm("mov.b64 {%0,%1}, %2;" : "=f"(c0), "=f"(c1) : "l"(acc[i][0]));
        asm("mov.b64 {%0,%1}, %2;" : "=f"(c2), "=f"(c3) : "l"(acc[i][1]));
        int col = col0 + tx*4;
        float* crow = C + (size_t)row*N;
        if (col+0 < N) crow[col+0] = c0 + bias[col+0];
        if (col+1 < N) crow[col+1] = c1 + bias[col+1];
        if (col+2 < N) crow[col+2] = c2 + bias[col+2];
        if (col+3 < N) crow[col+3] = c3 + bias[col+3];
    }
}

// ---------------------------------------------------------------------------
// Attention (unchanged)
// ---------------------------------------------------------------------------
__global__ void __launch_bounds__(256) attn_kernel(
        const float* __restrict__ src, const void* __restrict__ maskp,
        float* __restrict__ attn_out) {
    __shared__ float sq[Hd];
    __shared__ float ss[Slen];
    __shared__ float red[8];
    int row = blockIdx.x;
    int b = row / Tlen;
    int tid = threadIdx.x, lane = tid & 31, warp = tid >> 5;

    for (int h = tid; h < Hd; h += 256) sq[h] = g_q[row*Hd + h];
    __syncthreads();

    const unsigned char* m8  = (const unsigned char*)maskp;
    const int*           m32 = (const int*)maskp;
    int useu8 = g_mask_u8;

    for (int s = warp; s < Slen; s += 8) {
        const float* srow = src + ((size_t)b*Slen + s)*Hd;
        float p = 0.f;
        for (int h = lane; h < Hd; h += 32) p += sq[h]*srow[h];
        #pragma unroll
        for (int o = 16; o; o >>= 1) p += __shfl_xor_sync(0xffffffffu, p, o);
        if (lane == 0) {
            int mk = useu8 ? (int)m8[b*Slen + s] : m32[b*Slen + s];
            ss[s] = mk ? p : -1e9f;
        }
    }
    __syncthreads();

    float mv = -3.4e38f;
    for (int s = tid; s < Slen; s += 256) mv = fmaxf(mv, ss[s]);
    #pragma unroll
    for (int o = 16; o; o >>= 1) mv = fmaxf(mv, __shfl_xor_sync(0xffffffffu, mv, o));
    if (lane == 0) red[warp] = mv;
    __syncthreads();
    if (tid == 0) { float x = red[0]; for (int w = 1; w < 8; w++) x = fmaxf(x, red[w]); red[0] = x; }
    __syncthreads();
    float M = red[0];
    __syncthreads();

    float sv = 0.f;
    for (int s = tid; s < Slen; s += 256) { float e = __expf(ss[s] - M); ss[s] = e; sv += e; }
    #pragma unroll
    for (int o = 16; o; o >>= 1) sv += __shfl_xor_sync(0xffffffffu, sv, o);
    if (lane == 0) red[warp] = sv;
    __syncthreads();
    if (tid == 0) { float x = 0.f; for (int w = 0; w < 8; w++) x += red[w]; red[0] = x; }
    __syncthreads();
    float inv = 1.f / red[0];

    for (int s = tid; s < Slen; s += 256)
        attn_out[(size_t)row*Slen + s] = ss[s]*inv;

    for (int h = tid; h < Hd; h += 256) {
        float a0=0.f, a1=0.f, a2=0.f, a3=0.f;
        const float* sp = src + (size_t)b*Slen*Hd + h;
        for (int s = 0; s < Slen; s += 4) {
            a0 += ss[s  ]*sp[(size_t)(s  )*Hd];
            a1 += ss[s+1]*sp[(size_t)(s+1)*Hd];
            a2 += ss[s+2]*sp[(size_t)(s+2)*Hd];
            a3 += ss[s+3]*sp[(size_t)(s+3)*Hd];
        }
        g_cat[row*CATW + h] = (a0+a1+a2+a3)*inv;
    }
}

// ---------------------------------------------------------------------------
// p_gen (unchanged)
// ---------------------------------------------------------------------------
__global__ void pgen_kernel(const float* __restrict__ pW,
                            const float* __restrict__ pb) {
    int wg = blockIdx.x*(blockDim.x >> 5) + (threadIdx.x >> 5);
    if (wg >= ROWS) return;
    int lane = threadIdx.x & 31;
    const float* crow = g_cat + wg*CATW;
    float a0 = 0.f, a1 = 0.f;
    for (int k = lane; k < CATW; k += 32) {
        float v = crow[k];
        a0 += v*pW[k];
        a1 += v*pW[CATW + k];
    }
    #pragma unroll
    for (int o = 16; o; o >>= 1) {
        a0 += __shfl_xor_sync(0xffffffffu, a0, o);
        a1 += __shfl_xor_sync(0xffffffffu, a1, o);
    }
    if (lane == 0) {
        float l0 = a0 + pb[0], l1 = a1 + pb[1];
        float m = fmaxf(l0, l1);
        float e0 = __expf(l0 - m), e1 = __expf(l1 - m);
        float inv = 1.f/(e0 + e1);
        g_pgen[wg*2+0] = e0*inv;
        g_pgen[wg*2+1] = e1*inv;
    }
}

// ---------------------------------------------------------------------------
// Vocab softmax + final dist (unchanged)
// ---------------------------------------------------------------------------
__global__ void __launch_bounds__(256) softmax_final_kernel(float* __restrict__ out) {
    __shared__ float red[8];
    int row = blockIdx.x;
    const float* lrow = g_logits + (size_t)row*Vocab;
    int tid = threadIdx.x, lane = tid & 31, warp = tid >> 5;

    float mv = -3.4e38f;
    for (int v = tid; v < Vocab; v += 256) mv = fmaxf(mv, lrow[v]);
    #pragma unroll
    for (int o = 16; o; o >>= 1) mv = fmaxf(mv, __shfl_xor_sync(0xffffffffu, mv, o));
    if (lane == 0) red[warp] = mv;
    __syncthreads();
    if (tid == 0) { float x = red[0]; for (int w = 1; w < 8; w++) x = fmaxf(x, red[w]); red[0] = x; }
    __syncthreads();
    float M = red[0];
    __syncthreads();

    float sv = 0.f;
    for (int v = tid; v < Vocab; v += 256) sv += __expf(lrow[v] - M);
    #pragma unroll
    for (int o = 16; o; o >>= 1) sv += __shfl_xor_sync(0xffffffffu, sv, o);
    if (lane == 0) red[warp] = sv;
    __syncthreads();
    if (tid == 0) { float x = 0.f; for (int w = 0; w < 8; w++) x += red[w]; red[0] = x; }
    __syncthreads();
    float S = red[0];

    float scale = g_pgen[row*2] / S;
    float* orow = out + (size_t)row*VO;
    for (int v = tid; v < VO; v += 256)
        orow[v] = (v < Vocab) ? scale*__expf(lrow[v] - M) : 0.f;
}

// ---------------------------------------------------------------------------
// Copy-mechanism scatter (unchanged)
// ---------------------------------------------------------------------------
__global__ void scatter_kernel(float* __restrict__ out,
                               const int* __restrict__ src_oov,
                               const float* __restrict__ attn) {
    int row = blockIdx.x;
    int b = row / Tlen;
    float p1 = g_pgen[row*2+1];
    float* orow = out + (size_t)row*VO;
    for (int s = threadIdx.x; s < Slen; s += blockDim.x) {
        float a = attn[(size_t)row*Slen + s] * p1;
        int col = src_oov[b*Slen + s];
        atomicAdd(&orow[col], a);
    }
}

// ---------------------------------------------------------------------------
// Host launcher
// ---------------------------------------------------------------------------
extern "C" void kernel_launch(void* const* d_in, const int* in_sizes, int n_in,
                              void* d_out, int out_size) {
    int idx = 0;
    const int*   tokens  = (const int*)  d_in[idx++];
    const float* src     = (const float*)d_in[idx++];
    const void*  mask    =               d_in[idx++];
    const float* hidden0 = (const float*)d_in[idx++];
    const int*   src_oov = (const int*)  d_in[idx++];
    if (idx < n_in && in_sizes[idx] == 1) idx++;   // max_num_oov scalar (may be absent)
    const float* embed   = (const float*)d_in[idx++];
    const float* W_ih    = (const float*)d_in[idx++];
    const float* W_hh    = (const float*)d_in[idx++];
    const float* b_ih    = (const float*)d_in[idx++];
    const float* b_hh    = (const float*)d_in[idx++];
    const float* attn_W  = (const float*)d_in[idx++];
    const float* attn_b  = (const float*)d_in[idx++];
    const float* fc_W    = (const float*)d_in[idx++];
    const float* fc_b    = (const float*)d_in[idx++];
    const float* out_W   = (const float*)d_in[idx++];
    const float* out_b   = (const float*)d_in[idx++];
    const float* pgen_W  = (const float*)d_in[idx++];
    const float* pgen_b  = (const float*)d_in[idx++];

    float* out = (float*)d_out;
    float* attn_out;
    if (out_size >= (int)((size_t)ROWS*VO + (size_t)ROWS*Slen)) {
        attn_out = out + (size_t)ROWS*VO;          // [final_dist | attn_dist]
    } else {
        void* p = nullptr;
        cudaGetSymbolAddress(&p, g_attn_fallback);
        attn_out = (float*)p;
    }

    cudaFuncSetAttribute(gru_persistent_kernel,
                         cudaFuncAttributeMaxDynamicSharedMemorySize, SMEM_BYTES);

    detect_mask_kernel<<<1,1>>>((const unsigned char*)mask);
    init_hall_kernel<<<(Ld*Bsz*Hd+255)/256,256>>>(hidden0);
    embed_kernel<<<(ROWS*Ed+255)/256,256>>>(tokens, embed);

    gru_persistent_kernel<<<NBLK, NTHR, SMEM_BYTES>>>(W_ih, W_hh, b_ih, b_hh);

    gemm_kernel<<<dim3(5,8),256>>>(MODE_Q, attn_W, attn_b, Hd, Hd, CATW);
    attn_kernel<<<ROWS,256>>>(src, mask, attn_out);
    gemm_kernel<<<dim3(5,8),256>>>(MODE_FEAT, fc_W, fc_b, Hd, 2*Hd, CATW);
    gemm_kernel<<<dim3((Vocab+63)/64,8),256>>>(MODE_OUT, out_W, out_b, Vocab, Hd, Hd);
    pgen_kernel<<<64,256>>>(pgen_W, pgen_b);
    softmax_final_kernel<<<ROWS,256>>>(out);
    scatter_kernel<<<ROWS,256>>>(out, src_oov, attn_out);
}

// round 10
// speedup vs baseline: 2.2117x; 1.1246x over previous
#include <cuda_runtime.h>
#include <math.h>

// ---------------------------------------------------------------------------
// Problem constants
// ---------------------------------------------------------------------------
#define Bsz   32
#define Tlen  16
#define Slen  400
#define Hd    300
#define Ed    300
#define Ld    3
#define Vocab 50000
#define OOV   20
#define ROWS  (Bsz*Tlen)      // 512
#define VO    (Vocab+OOV)     // 50020
#define CATW  900             // [contexts(300) | hiddens(300) | x(300)]

// Persistent GRU config
#define NBLK  100
#define NTHR  864             // 27 warps = 9 task-pairs x 3 k-thirds
#define NJ    3
#define SB    302             // activation stride [b][k]: LDS.64 conflict-free

// GRU smem layout (floats)
#define SW_FLOATS   16200     // 3 layers * 18 tasks * 300
#define SX_OFF      16200
#define SH_OFF      (SX_OFF + Bsz*SB)
#define SACC_OFF    (SH_OFF + Bsz*SB)
#define SMEM_FLOATS (SACC_OFF + 18*96)
#define SMEM_BYTES  (SMEM_FLOATS*4)

#define FMA2(acc, x, y) asm("fma.rn.f32x2 %0, %1, %2, %0;" : "+l"(acc) : "l"(x), "l"(y))

// ---------------------------------------------------------------------------
// Scratch
// ---------------------------------------------------------------------------
__device__ float g_cat[ROWS*CATW];
__device__ float g_hall[Ld][Tlen+1][Bsz][Hd];
__device__ float g_q[ROWS*Hd];
__device__ float g_feat[ROWS*Hd];
__device__ float g_logits[(size_t)ROWS*Vocab];     // holds exp(logit) after out-GEMM
__device__ float g_rowsum[ROWS];
__device__ float g_pgen[ROWS*2];
__device__ float g_attn_fallback[ROWS*Slen];
__device__ int   g_mask_u8;

__device__ unsigned g_bar_cnt = 0;
__device__ unsigned g_bar_gen = 0;

// ---------------------------------------------------------------------------
__global__ void detect_mask_kernel(const unsigned char* __restrict__ m) {
    g_mask_u8 = (m[1] | m[2] | m[3]) ? 1 : 0;
}

__global__ void init_hall_kernel(const float* __restrict__ h0) {
    int i = blockIdx.x*blockDim.x + threadIdx.x;
    if (i < Ld*Bsz*Hd) {
        int l = i / (Bsz*Hd), r = i - l*(Bsz*Hd);
        (&g_hall[l][0][0][0])[r] = h0[i];
    }
    if (i < ROWS) g_rowsum[i] = 0.f;    // re-zeroed every launch (graph replay safe)
}

__global__ void embed_kernel(const int* __restrict__ tokens,
                             const float* __restrict__ embed) {
    int i = blockIdx.x*blockDim.x + threadIdx.x;
    if (i < ROWS*Ed) {
        int row = i / Ed, e = i - row*Ed;
        g_cat[row*CATW + 600 + e] = embed[(size_t)tokens[row]*Ed + e];
    }
}

// ---------------------------------------------------------------------------
// Grid barrier
// ---------------------------------------------------------------------------
__device__ __forceinline__ void grid_barrier() {
    __threadfence();
    __syncthreads();
    if (threadIdx.x == 0) {
        unsigned gen = *(volatile unsigned*)&g_bar_gen;
        if (atomicAdd(&g_bar_cnt, 1u) == NBLK - 1u) {
            atomicExch(&g_bar_cnt, 0u);
            __threadfence();
            atomicAdd(&g_bar_gen, 1u);
        } else {
            while (*(volatile unsigned*)&g_bar_gen == gen) __nanosleep(32);
        }
        __threadfence();
    }
    __syncthreads();
}

// ---------------------------------------------------------------------------
// Persistent GRU v4: 27 warps; warp w -> pair p = w/3, third q = w%3.
// Pair p covers tasks (2p, 2p+1); k-range [q*100, q*100+100).
// Task id: m*9 + g*3 + jl   (m: 0=ih 1=hh; g: 0=r 1=z 2=n; jl: 0..2)
// ---------------------------------------------------------------------------
extern __shared__ float s_dyn[];

__global__ void __launch_bounds__(NTHR) gru_persistent_kernel(
        const float* __restrict__ W_ih, const float* __restrict__ W_hh,
        const float* __restrict__ b_ih, const float* __restrict__ b_hh) {
    float* sw   = s_dyn;
    float* sx   = s_dyn + SX_OFF;
    float* sh   = s_dyn + SH_OFF;
    float* sacc = s_dyn + SACC_OFF;

    const int tid  = threadIdx.x;
    const int j0   = blockIdx.x * NJ;
    const int lane = tid & 31, w = tid >> 5;
    const int p = w / 3, q = w - 3*p;
    const int tA = 2*p, tB = tA + 1;
    const int kbeg = q * 100;
    const int kend = kbeg + 100;

    for (int idx = tid; idx < SW_FLOATS; idx += NTHR) {
        int l = idx / 5400, r = idx - l*5400;
        int task = r / 300, k = r - task*300;
        int m = task / 9, t2 = task - m*9;
        int g = t2 / 3, jl = t2 - g*3;
        int row = g*300 + j0 + jl;
        const float* src = (m == 0) ? W_ih : W_hh;
        sw[idx] = src[(size_t)l*270000 + (size_t)row*300 + k];
    }

    for (int wf = 0; wf < Tlen + Ld - 1; wf++) {
        int lmin = wf - (Tlen-1); if (lmin < 0) lmin = 0;
        int lmax = (wf < Ld-1) ? wf : Ld-1;
        for (int l = lmin; l <= lmax; l++) {
            int t = wf - l;
            const float* xsrc; int xstr;
            if (l == 0) { xsrc = g_cat + t*CATW + 600; xstr = Tlen*CATW; }
            else        { xsrc = &g_hall[l-1][t+1][0][0]; xstr = Hd; }
            const float* hsrc = &g_hall[l][t][0][0];

            __syncthreads();
            for (int i = tid; i < Bsz*75; i += NTHR) {
                int b = i / 75, q4 = (i - b*75)*4;
                float4 xv = *(const float4*)(xsrc + (size_t)b*xstr + q4);
                float4 hv = *(const float4*)(hsrc + b*Hd + q4);
                *(float2*)&sx[b*SB + q4    ] = make_float2(xv.x, xv.y);
                *(float2*)&sx[b*SB + q4 + 2] = make_float2(xv.z, xv.w);
                *(float2*)&sh[b*SB + q4    ] = make_float2(hv.x, hv.y);
                *(float2*)&sh[b*SB + q4 + 2] = make_float2(hv.z, hv.w);
            }
            __syncthreads();

            {
                const float* wA = sw + (l*18 + tA)*300;
                const float* wB = sw + (l*18 + tB)*300;
                const float* aA = ((tA < 9) ? sx : sh) + lane*SB;
                const float* aB = ((tB < 9) ? sx : sh) + lane*SB;
                unsigned long long accA0 = 0ull, accA1 = 0ull;
                unsigned long long accB0 = 0ull, accB1 = 0ull;
                int k = kbeg;
                if (p != 4) {   // shared activation stream
                    for (; k + 8 <= kend; k += 8) {
                        ulonglong2 wa0 = *(const ulonglong2*)(wA + k);
                        ulonglong2 wa1 = *(const ulonglong2*)(wA + k + 4);
                        ulonglong2 wb0 = *(const ulonglong2*)(wB + k);
                        ulonglong2 wb1 = *(const ulonglong2*)(wB + k + 4);
                        unsigned long long x0 = *(const unsigned long long*)(aA + k);
                        unsigned long long x1 = *(const unsigned long long*)(aA + k + 2);
                        unsigned long long x2 = *(const unsigned long long*)(aA + k + 4);
                        unsigned long long x3 = *(const unsigned long long*)(aA + k + 6);
                        FMA2(accA0, wa0.x, x0); FMA2(accA1, wa0.y, x1);
                        FMA2(accB0, wb0.x, x0); FMA2(accB1, wb0.y, x1);
                        FMA2(accA0, wa1.x, x2); FMA2(accA1, wa1.y, x3);
                        FMA2(accB0, wb1.x, x2); FMA2(accB1, wb1.y, x3);
                    }
                    if (k < kend) {
                        ulonglong2 wa = *(const ulonglong2*)(wA + k);
                        ulonglong2 wb = *(const ulonglong2*)(wB + k);
                        unsigned long long x0 = *(const unsigned long long*)(aA + k);
                        unsigned long long x1 = *(const unsigned long long*)(aA + k + 2);
                        FMA2(accA0, wa.x, x0); FMA2(accA1, wa.y, x1);
                        FMA2(accB0, wb.x, x0); FMA2(accB1, wb.y, x1);
                    }
                } else {        // mixed pair (task 8 reads x, task 9 reads h)
                    for (; k + 8 <= kend; k += 8) {
                        ulonglong2 wa0 = *(const ulonglong2*)(wA + k);
                        ulonglong2 wa1 = *(const ulonglong2*)(wA + k + 4);
                        ulonglong2 wb0 = *(const ulonglong2*)(wB + k);
                        ulonglong2 wb1 = *(const ulonglong2*)(wB + k + 4);
                        unsigned long long x0 = *(const unsigned long long*)(aA + k);
                        unsigned long long x1 = *(const unsigned long long*)(aA + k + 2);
                        unsigned long long x2 = *(const unsigned long long*)(aA + k + 4);
                        unsigned long long x3 = *(const unsigned long long*)(aA + k + 6);
                        unsigned long long y0 = *(const unsigned long long*)(aB + k);
                        unsigned long long y1 = *(const unsigned long long*)(aB + k + 2);
                        unsigned long long y2 = *(const unsigned long long*)(aB + k + 4);
                        unsigned long long y3 = *(const unsigned long long*)(aB + k + 6);
                        FMA2(accA0, wa0.x, x0); FMA2(accA1, wa0.y, x1);
                        FMA2(accB0, wb0.x, y0); FMA2(accB1, wb0.y, y1);
                        FMA2(accA0, wa1.x, x2); FMA2(accA1, wa1.y, x3);
                        FMA2(accB0, wb1.x, y2); FMA2(accB1, wb1.y, y3);
                    }
                    if (k < kend) {
                        ulonglong2 wa = *(const ulonglong2*)(wA + k);
                        ulonglong2 wb = *(const ulonglong2*)(wB + k);
                        unsigned long long x0 = *(const unsigned long long*)(aA + k);
                        unsigned long long x1 = *(const unsigned long long*)(aA + k + 2);
                        unsigned long long y0 = *(const unsigned long long*)(aB + k);
                        unsigned long long y1 = *(const unsigned long long*)(aB + k + 2);
                        FMA2(accA0, wa.x, x0); FMA2(accA1, wa.y, x1);
                        FMA2(accB0, wb.x, y0); FMA2(accB1, wb.y, y1);
                    }
                }
                float a0,a1,a2,a3;
                asm("mov.b64 {%0,%1}, %2;" : "=f"(a0), "=f"(a1) : "l"(accA0));
                asm("mov.b64 {%0,%1}, %2;" : "=f"(a2), "=f"(a3) : "l"(accA1));
                sacc[tA*96 + q*32 + lane] = (a0+a1) + (a2+a3);
                asm("mov.b64 {%0,%1}, %2;" : "=f"(a0), "=f"(a1) : "l"(accB0));
                asm("mov.b64 {%0,%1}, %2;" : "=f"(a2), "=f"(a3) : "l"(accB1));
                sacc[tB*96 + q*32 + lane] = (a0+a1) + (a2+a3);
            }
            __syncthreads();

            if (tid < 96) {
                int b = tid & 31, jl = tid >> 5;
                int j = j0 + jl;
                #define SAC(tk) (sacc[(tk)*96+b] + sacc[(tk)*96+32+b] + sacc[(tk)*96+64+b])
                float i_r = SAC( 0+jl) + b_ih[l*900 +       j];
                float i_z = SAC( 3+jl) + b_ih[l*900 + 300 + j];
                float i_n = SAC( 6+jl) + b_ih[l*900 + 600 + j];
                float h_r = SAC( 9+jl) + b_hh[l*900 +       j];
                float h_z = SAC(12+jl) + b_hh[l*900 + 300 + j];
                float h_n = SAC(15+jl) + b_hh[l*900 + 600 + j];
                #undef SAC
                float r = 1.f/(1.f + __expf(-(i_r + h_r)));
                float z = 1.f/(1.f + __expf(-(i_z + h_z)));
                float n = tanhf(i_n + r*h_n);
                float hp = g_hall[l][t][b][j];
                float hv = (1.f - z)*n + z*hp;
                g_hall[l][t+1][b][j] = hv;
                if (l == Ld-1) g_cat[(b*Tlen + t)*CATW + 300 + j] = hv;
            }
        }
        grid_barrier();
    }
}

// ---------------------------------------------------------------------------
// Small GEMM (Q / FEAT only): unchanged 4x4 kernel from R9.
// ---------------------------------------------------------------------------
#define MODE_Q    0
#define MODE_FEAT 1
#define TS 68

__global__ void __launch_bounds__(256) gemm_kernel(
        int mode, const float* __restrict__ W, const float* __restrict__ bias,
        int N, int K, int lda) {
    const float* A; float* C;
    if (mode == MODE_Q) { A = g_cat + 300; C = g_q; }
    else                { A = g_cat;       C = g_feat; }

    __shared__ __align__(16) float As[30*TS];
    __shared__ __align__(16) float Bs[30*TS];
    int tid = threadIdx.x;
    int tx = tid & 15, ty = tid >> 4;
    int row0 = blockIdx.y*64, col0 = blockIdx.x*64;

    unsigned long long acc[4][2];
    #pragma unroll
    for (int i = 0; i < 4; i++) { acc[i][0] = 0ull; acc[i][1] = 0ull; }

    for (int k0 = 0; k0 < K; k0 += 30) {
        for (int i = tid; i < 64*30; i += 256) {
            int m = i/30, k = i - m*30;
            As[k*TS + m] = A[(size_t)(row0+m)*lda + k0 + k];
            int col = col0 + m;
            Bs[k*TS + m] = (col < N) ? W[(size_t)col*K + k0 + k] : 0.f;
        }
        __syncthreads();
        #pragma unroll
        for (int k = 0; k < 30; k++) {
            float4 av = *(const float4*)&As[k*TS + ty*4];
            float4 bv = *(const float4*)&Bs[k*TS + tx*4];
            unsigned long long b01, b23;
            asm("mov.b64 %0, {%1,%2};" : "=l"(b01) : "f"(bv.x), "f"(bv.y));
            asm("mov.b64 %0, {%1,%2};" : "=l"(b23) : "f"(bv.z), "f"(bv.w));
            float aarr[4] = {av.x, av.y, av.z, av.w};
            #pragma unroll
            for (int i = 0; i < 4; i++) {
                unsigned long long ap;
                asm("mov.b64 %0, {%1,%1};" : "=l"(ap) : "f"(aarr[i]));
                FMA2(acc[i][0], ap, b01);
                FMA2(acc[i][1], ap, b23);
            }
        }
        __syncthreads();
    }
    #pragma unroll
    for (int i = 0; i < 4; i++) {
        int row = row0 + ty*4 + i;
        float c0,c1,c2,c3;
        asm("mov.b64 {%0,%1}, %2;" : "=f"(c0), "=f"(c1) : "l"(acc[i][0]));
        asm("mov.b64 {%0,%1}, %2;" : "=f"(c2), "=f"(c3) : "l"(acc[i][1]));
        int col = col0 + tx*4;
        float* crow = C + (size_t)row*N;
        if (col+0 < N) crow[col+0] = c0 + bias[col+0];
        if (col+1 < N) crow[col+1] = c1 + bias[col+1];
        if (col+2 < N) crow[col+2] = c2 + bias[col+2];
        if (col+3 < N) crow[col+3] = c3 + bias[col+3];
    }
}

// ---------------------------------------------------------------------------
// OUT GEMM: C = g_feat[512,300] @ out_W^T[300,50000], 8x8 micro-tile,
// 128x128 block tile, K-chunk 20. A-pairs packed naturally (m-adjacent);
// B in swizzled chunk layout (offset 36*(c>>2)+8*(c&3), row stride 148) ->
// minimal-wavefront LDS.128. Epilogue: exp(logit+bias) stored to g_logits,
// per-row partial sums shuffle-reduced -> g_rowsum atomics.
// ---------------------------------------------------------------------------
#define OKC  20
#define ASTR 132
#define BSTR 148

__global__ void __launch_bounds__(256) out_gemm_kernel(
        const float* __restrict__ W, const float* __restrict__ bias) {
    __shared__ __align__(16) float As[OKC*ASTR];
    __shared__ __align__(16) float Bs[OKC*BSTR];
    const int tid = threadIdx.x;
    const int tx = tid & 15, ty = tid >> 4;
    const int row0 = blockIdx.y*128, col0 = blockIdx.x*128;

    unsigned long long acc[8][4];   // [j][m-pair]
    #pragma unroll
    for (int j = 0; j < 8; j++)
        #pragma unroll
        for (int mp = 0; mp < 4; mp++) acc[j][mp] = 0ull;

    for (int k0 = 0; k0 < 300; k0 += OKC) {
        for (int i = tid; i < 128*OKC; i += 256) {
            int m = i / OKC, k = i - m*OKC;
            As[k*ASTR + m] = g_feat[(size_t)(row0+m)*300 + k0 + k];
        }
        for (int i = tid; i < 128*OKC; i += 256) {
            int n = i / OKC, k = i - n*OKC;
            int c = n >> 3, o = n & 7;
            int col = col0 + n;
            float v = (col < Vocab) ? W[(size_t)col*300 + k0 + k] : 0.f;
            Bs[k*BSTR + 36*(c>>2) + 8*(c&3) + o] = v;
        }
        __syncthreads();
        #pragma unroll 4
        for (int k = 0; k < OKC; k++) {
            ulonglong2 a01 = *(const ulonglong2*)&As[k*ASTR + ty*8];
            ulonglong2 a23 = *(const ulonglong2*)&As[k*ASTR + ty*8 + 4];
            const float* bb = &Bs[k*BSTR + 36*(tx>>2) + 8*(tx&3)];
            float4 b0 = *(const float4*)bb;
            float4 b1 = *(const float4*)(bb + 4);
            unsigned long long bd[8];
            asm("mov.b64 %0, {%1,%1};" : "=l"(bd[0]) : "f"(b0.x));
            asm("mov.b64 %0, {%1,%1};" : "=l"(bd[1]) : "f"(b0.y));
            asm("mov.b64 %0, {%1,%1};" : "=l"(bd[2]) : "f"(b0.z));
            asm("mov.b64 %0, {%1,%1};" : "=l"(bd[3]) : "f"(b0.w));
            asm("mov.b64 %0, {%1,%1};" : "=l"(bd[4]) : "f"(b1.x));
            asm("mov.b64 %0, {%1,%1};" : "=l"(bd[5]) : "f"(b1.y));
            asm("mov.b64 %0, {%1,%1};" : "=l"(bd[6]) : "f"(b1.z));
            asm("mov.b64 %0, {%1,%1};" : "=l"(bd[7]) : "f"(b1.w));
            #pragma unroll
            for (int j = 0; j < 8; j++) {
                FMA2(acc[j][0], a01.x, bd[j]);
                FMA2(acc[j][1], a01.y, bd[j]);
                FMA2(acc[j][2], a23.x, bd[j]);
                FMA2(acc[j][3], a23.y, bd[j]);
            }
        }
        __syncthreads();
    }

    // epilogue: exp + store + row-sum
    const int cb = col0 + tx*8;
    float bs_[8];
    #pragma unroll
    for (int j = 0; j < 8; j++) bs_[j] = (cb + j < Vocab) ? bias[cb + j] : 0.f;

    #pragma unroll
    for (int mp = 0; mp < 4; mp++) {
        #pragma unroll
        for (int hh = 0; hh < 2; hh++) {
            int r = ty*8 + 2*mp + hh;
            float e[8];
            #pragma unroll
            for (int j = 0; j < 8; j++) {
                float lo, hi;
                asm("mov.b64 {%0,%1}, %2;" : "=f"(lo), "=f"(hi) : "l"(acc[j][mp]));
                float v = hh ? hi : lo;
                e[j] = (cb + j < Vocab) ? __expf(v + bs_[j]) : 0.f;
            }
            float s = e[0]+e[1]+e[2]+e[3]+e[4]+e[5]+e[6]+e[7];
            #pragma unroll
            for (int o = 8; o; o >>= 1) s += __shfl_xor_sync(0xffffffffu, s, o, 16);
            float* crow = g_logits + (size_t)(row0 + r)*Vocab + cb;
            if (cb + 7 < Vocab) {
                *(float4*)crow       = make_float4(e[0], e[1], e[2], e[3]);
                *(float4*)(crow + 4) = make_float4(e[4], e[5], e[6], e[7]);
            } else {
                #pragma unroll
                for (int j = 0; j < 8; j++)
                    if (cb + j < Vocab) crow[j] = e[j];
            }
            if ((tid & 15) == 0) atomicAdd(&g_rowsum[row0 + r], s);
        }
    }
}

// ---------------------------------------------------------------------------
// Attention (unchanged)
// ---------------------------------------------------------------------------
__global__ void __launch_bounds__(256) attn_kernel(
        const float* __restrict__ src, const void* __restrict__ maskp,
        float* __restrict__ attn_out) {
    __shared__ float sq[Hd];
    __shared__ float ss[Slen];
    __shared__ float red[8];
    int row = blockIdx.x;
    int b = row / Tlen;
    int tid = threadIdx.x, lane = tid & 31, warp = tid >> 5;

    for (int h = tid; h < Hd; h += 256) sq[h] = g_q[row*Hd + h];
    __syncthreads();

    const unsigned char* m8  = (const unsigned char*)maskp;
    const int*           m32 = (const int*)maskp;
    int useu8 = g_mask_u8;

    for (int s = warp; s < Slen; s += 8) {
        const float* srow = src + ((size_t)b*Slen + s)*Hd;
        float p = 0.f;
        for (int h = lane; h < Hd; h += 32) p += sq[h]*srow[h];
        #pragma unroll
        for (int o = 16; o; o >>= 1) p += __shfl_xor_sync(0xffffffffu, p, o);
        if (lane == 0) {
            int mk = useu8 ? (int)m8[b*Slen + s] : m32[b*Slen + s];
            ss[s] = mk ? p : -1e9f;
        }
    }
    __syncthreads();

    float mv = -3.4e38f;
    for (int s = tid; s < Slen; s += 256) mv = fmaxf(mv, ss[s]);
    #pragma unroll
    for (int o = 16; o; o >>= 1) mv = fmaxf(mv, __shfl_xor_sync(0xffffffffu, mv, o));
    if (lane == 0) red[warp] = mv;
    __syncthreads();
    if (tid == 0) { float x = red[0]; for (int w = 1; w < 8; w++) x = fmaxf(x, red[w]); red[0] = x; }
    __syncthreads();
    float M = red[0];
    __syncthreads();

    float sv = 0.f;
    for (int s = tid; s < Slen; s += 256) { float e = __expf(ss[s] - M); ss[s] = e; sv += e; }
    #pragma unroll
    for (int o = 16; o; o >>= 1) sv += __shfl_xor_sync(0xffffffffu, sv, o);
    if (lane == 0) red[warp] = sv;
    __syncthreads();
    if (tid == 0) { float x = 0.f; for (int w = 0; w < 8; w++) x += red[w]; red[0] = x; }
    __syncthreads();
    float inv = 1.f / red[0];

    for (int s = tid; s < Slen; s += 256)
        attn_out[(size_t)row*Slen + s] = ss[s]*inv;

    for (int h = tid; h < Hd; h += 256) {
        float a0=0.f, a1=0.f, a2=0.f, a3=0.f;
        const float* sp = src + (size_t)b*Slen*Hd + h;
        for (int s = 0; s < Slen; s += 4) {
            a0 += ss[s  ]*sp[(size_t)(s  )*Hd];
            a1 += ss[s+1]*sp[(size_t)(s+1)*Hd];
            a2 += ss[s+2]*sp[(size_t)(s+2)*Hd];
            a3 += ss[s+3]*sp[(size_t)(s+3)*Hd];
        }
        g_cat[row*CATW + h] = (a0+a1+a2+a3)*inv;
    }
}

// ---------------------------------------------------------------------------
// p_gen (unchanged)
// ---------------------------------------------------------------------------
__global__ void pgen_kernel(const float* __restrict__ pW,
                            const float* __restrict__ pb) {
    int wg = blockIdx.x*(blockDim.x >> 5) + (threadIdx.x >> 5);
    if (wg >= ROWS) return;
    int lane = threadIdx.x & 31;
    const float* crow = g_cat + wg*CATW;
    float a0 = 0.f, a1 = 0.f;
    for (int k = lane; k < CATW; k += 32) {
        float v = crow[k];
        a0 += v*pW[k];
        a1 += v*pW[CATW + k];
    }
    #pragma unroll
    for (int o = 16; o; o >>= 1) {
        a0 += __shfl_xor_sync(0xffffffffu, a0, o);
        a1 += __shfl_xor_sync(0xffffffffu, a1, o);
    }
    if (lane == 0) {
        float l0 = a0 + pb[0], l1 = a1 + pb[1];
        float m = fmaxf(l0, l1);
        float e0 = __expf(l0 - m), e1 = __expf(l1 - m);
        float inv = 1.f/(e0 + e1);
        g_pgen[wg*2+0] = e0*inv;
        g_pgen[wg*2+1] = e1*inv;
    }
}

// ---------------------------------------------------------------------------
// Final scale: out = pgen0 * exp_logit / rowsum ; OOV cols = 0.
// ---------------------------------------------------------------------------
__global__ void __launch_bounds__(256) scale_final_kernel(float* __restrict__ out) {
    int row = blockIdx.x;
    float scale = g_pgen[row*2] / g_rowsum[row];
    const float* lrow = g_logits + (size_t)row*Vocab;
    float* orow = out + (size_t)row*VO;
    for (int v = threadIdx.x; v < VO; v += 256)
        orow[v] = (v < Vocab) ? scale*lrow[v] : 0.f;
}

// ---------------------------------------------------------------------------
// Copy-mechanism scatter (unchanged)
// ---------------------------------------------------------------------------
__global__ void scatter_kernel(float* __restrict__ out,
                               const int* __restrict__ src_oov,
                               const float* __restrict__ attn) {
    int row = blockIdx.x;
    int b = row / Tlen;
    float p1 = g_pgen[row*2+1];
    float* orow = out + (size_t)row*VO;
    for (int s = threadIdx.x; s < Slen; s += blockDim.x) {
        float a = attn[(size_t)row*Slen + s] * p1;
        int col = src_oov[b*Slen + s];
        atomicAdd(&orow[col], a);
    }
}

// ---------------------------------------------------------------------------
// Host launcher
// ---------------------------------------------------------------------------
extern "C" void kernel_launch(void* const* d_in, const int* in_sizes, int n_in,
                              void* d_out, int out_size) {
    int idx = 0;
    const int*   tokens  = (const int*)  d_in[idx++];
    const float* src     = (const float*)d_in[idx++];
    const void*  mask    =               d_in[idx++];
    const float* hidden0 = (const float*)d_in[idx++];
    const int*   src_oov = (const int*)  d_in[idx++];
    if (idx < n_in && in_sizes[idx] == 1) idx++;   // max_num_oov scalar
    const float* embed   = (const float*)d_in[idx++];
    const float* W_ih    = (const float*)d_in[idx++];
    const float* W_hh    = (const float*)d_in[idx++];
    const float* b_ih    = (const float*)d_in[idx++];
    const float* b_hh    = (const float*)d_in[idx++];
    const float* attn_W  = (const float*)d_in[idx++];
    const float* attn_b  = (const float*)d_in[idx++];
    const float* fc_W    = (const float*)d_in[idx++];
    const float* fc_b    = (const float*)d_in[idx++];
    const float* out_W   = (const float*)d_in[idx++];
    const float* out_b   = (const float*)d_in[idx++];
    const float* pgen_W  = (const float*)d_in[idx++];
    const float* pgen_b  = (const float*)d_in[idx++];

    float* out = (float*)d_out;
    float* attn_out;
    if (out_size >= (int)((size_t)ROWS*VO + (size_t)ROWS*Slen)) {
        attn_out = out + (size_t)ROWS*VO;
    } else {
        void* p = nullptr;
        cudaGetSymbolAddress(&p, g_attn_fallback);
        attn_out = (float*)p;
    }

    cudaFuncSetAttribute(gru_persistent_kernel,
                         cudaFuncAttributeMaxDynamicSharedMemorySize, SMEM_BYTES);

    detect_mask_kernel<<<1,1>>>((const unsigned char*)mask);
    init_hall_kernel<<<(Ld*Bsz*Hd+255)/256,256>>>(hidden0);
    embed_kernel<<<(ROWS*Ed+255)/256,256>>>(tokens, embed);

    gru_persistent_kernel<<<NBLK, NTHR, SMEM_BYTES>>>(W_ih, W_hh, b_ih, b_hh);

    gemm_kernel<<<dim3(5,8),256>>>(MODE_Q, attn_W, attn_b, Hd, Hd, CATW);
    attn_kernel<<<ROWS,256>>>(src, mask, attn_out);
    gemm_kernel<<<dim3(5,8),256>>>(MODE_FEAT, fc_W, fc_b, Hd, 2*Hd, CATW);
    out_gemm_kernel<<<dim3((Vocab+127)/128, 4),256>>>(out_W, out_b);
    pgen_kernel<<<64,256>>>(pgen_W, pgen_b);
    scale_final_kernel<<<ROWS,256>>>(out);
    scatter_kernel<<<ROWS,256>>>(out, src_oov, attn_out);
}

// round 12
// speedup vs baseline: 2.6007x; 1.1759x over previous
#include <cuda_runtime.h>
#include <math.h>

// ---------------------------------------------------------------------------
// Problem constants
// ---------------------------------------------------------------------------
#define Bsz   32
#define Tlen  16
#define Slen  400
#define Hd    300
#define Ed    300
#define Ld    3
#define Vocab 50000
#define OOV   20
#define ROWS  (Bsz*Tlen)      // 512
#define VO    (Vocab+OOV)     // 50020
#define CATW  900             // [contexts(300) | hiddens(300) | x(300)]

// Persistent GRU config
#define NBLK  100
#define NTHR  864             // 27 warps = 9 task-pairs x 3 k-thirds
#define NJ    3
#define SB    308             // activation stride: LDS.128 conflict-free (lane*77 mod 8 distinct)

// GRU smem layout (floats)
#define SW_FLOATS   16200     // 3 layers * 18 tasks * 300
#define SX_OFF      16200
#define SH_OFF      (SX_OFF + Bsz*SB)          // 26056
#define SACC_OFF    (SH_OFF + Bsz*SB)          // 35912
#define SBIAS_OFF   (SACC_OFF + 18*96)         // 37640
#define SMEM_FLOATS (SBIAS_OFF + 54)           // 37694
#define SMEM_BYTES  (SMEM_FLOATS*4)            // 150776

#define FMA2(acc, x, y) asm("fma.rn.f32x2 %0, %1, %2, %0;" : "+l"(acc) : "l"(x), "l"(y))

// ---------------------------------------------------------------------------
// Scratch
// ---------------------------------------------------------------------------
__device__ float g_cat[ROWS*CATW];
__device__ float g_hall[Ld][Tlen+1][Bsz][Hd];
__device__ float g_q[ROWS*Hd];
__device__ float g_feat[ROWS*Hd];
__device__ float g_logits[(size_t)ROWS*Vocab];     // exp(logit) after out-GEMM
__device__ float g_rowsum[ROWS];
__device__ float g_pgen[ROWS*2];
__device__ float g_attn_fallback[ROWS*Slen];
__device__ int   g_mask_u8;

__device__ unsigned g_bar_cnt = 0;
__device__ unsigned g_bar_gen = 0;

// ---------------------------------------------------------------------------
__global__ void detect_mask_kernel(const unsigned char* __restrict__ m) {
    g_mask_u8 = (m[1] | m[2] | m[3]) ? 1 : 0;
}

__global__ void init_hall_kernel(const float* __restrict__ h0) {
    int i = blockIdx.x*blockDim.x + threadIdx.x;
    if (i < Ld*Bsz*Hd) {
        int l = i / (Bsz*Hd), r = i - l*(Bsz*Hd);
        (&g_hall[l][0][0][0])[r] = h0[i];
    }
    if (i < ROWS) g_rowsum[i] = 0.f;    // re-zeroed every launch (graph replay safe)
}

__global__ void embed_kernel(const int* __restrict__ tokens,
                             const float* __restrict__ embed) {
    int i = blockIdx.x*blockDim.x + threadIdx.x;
    if (i < ROWS*Ed) {
        int row = i / Ed, e = i - row*Ed;
        g_cat[row*CATW + 600 + e] = embed[(size_t)tokens[row]*Ed + e];
    }
}

// ---------------------------------------------------------------------------
// Grid barrier
// ---------------------------------------------------------------------------
__device__ __forceinline__ void grid_barrier() {
    __threadfence();
    __syncthreads();
    if (threadIdx.x == 0) {
        unsigned gen = *(volatile unsigned*)&g_bar_gen;
        if (atomicAdd(&g_bar_cnt, 1u) == NBLK - 1u) {
            atomicExch(&g_bar_cnt, 0u);
            __threadfence();
            atomicAdd(&g_bar_gen, 1u);
        } else {
            while (*(volatile unsigned*)&g_bar_gen == gen) __nanosleep(32);
        }
        __threadfence();
    }
    __syncthreads();
}

// ---------------------------------------------------------------------------
// GRU activation prefetch (registers). Cell (l,t): x-source + hprev.
// ---------------------------------------------------------------------------
__device__ __forceinline__ void gru_prefetch(int l, int t, int tid,
                                             float4* px, float4* ph) {
    const float* xsrc; size_t xstr;
    if (l == 0) { xsrc = g_cat + t*CATW + 600; xstr = Tlen*CATW; }
    else        { xsrc = &g_hall[l-1][t+1][0][0]; xstr = Hd; }
    const float* hsrc = &g_hall[l][t][0][0];
    #pragma unroll
    for (int it = 0; it < 3; it++) {
        int i = tid + it*NTHR;
        if (i < Bsz*75) {
            int b = i / 75, q4 = (i - b*75)*4;
            px[it] = *(const float4*)(xsrc + (size_t)b*xstr + q4);
            ph[it] = *(const float4*)(hsrc + b*Hd + q4);
        }
    }
}

// ---------------------------------------------------------------------------
// Persistent GRU v5.1: identical to v5 except the RACE FIX — each non-first
// cell in a wavefront begins with a __syncthreads() so the previous cell's
// combine (reads sh for hprev, tid<96 only) drains before sx/sh are restaged.
// ---------------------------------------------------------------------------
extern __shared__ float s_dyn[];

__global__ void __launch_bounds__(NTHR) gru_persistent_kernel(
        const float* __restrict__ W_ih, const float* __restrict__ W_hh,
        const float* __restrict__ b_ih, const float* __restrict__ b_hh) {
    float* sw   = s_dyn;
    float* sx   = s_dyn + SX_OFF;
    float* sh   = s_dyn + SH_OFF;
    float* sacc = s_dyn + SACC_OFF;
    float* sb   = s_dyn + SBIAS_OFF;

    const int tid  = threadIdx.x;
    const int j0   = blockIdx.x * NJ;
    const int lane = tid & 31, w = tid >> 5;
    const int p = w / 3, q = w - 3*p;
    const int tA = 2*p, tB = tA + 1;
    const int kbeg = q * 100;

    // Weights (once) + biases (once)
    for (int idx = tid; idx < SW_FLOATS; idx += NTHR) {
        int l = idx / 5400, r = idx - l*5400;
        int task = r / 300, k = r - task*300;
        int m = task / 9, t2 = task - m*9;
        int g = t2 / 3, jl = t2 - g*3;
        int row = g*300 + j0 + jl;
        const float* src = (m == 0) ? W_ih : W_hh;
        sw[idx] = src[(size_t)l*270000 + (size_t)row*300 + k];
    }
    if (tid < 54) {
        int l = tid / 18, r = tid % 18;
        int m = r / 9, r2 = r % 9;
        int g = r2 / 3, jl = r2 % 3;
        const float* src = m ? b_hh : b_ih;
        sb[tid] = src[l*900 + g*300 + j0 + jl];
    }

    float4 px[3], ph[3];
    gru_prefetch(0, 0, tid, px, ph);

    for (int wf = 0; wf < Tlen + Ld - 1; wf++) {
        int lmin = wf - (Tlen-1); if (lmin < 0) lmin = 0;
        int lmax = (wf < Ld-1) ? wf : Ld-1;
        for (int l = lmin; l <= lmax; l++) {
            int t = wf - l;

            // RACE FIX: drain previous cell's combine readers of sh before
            // restaging (first cell of a wavefront is covered by grid_barrier)
            if (l != lmin) __syncthreads();

            // STS prefetched activations
            #pragma unroll
            for (int it = 0; it < 3; it++) {
                int i = tid + it*NTHR;
                if (i < Bsz*75) {
                    int b = i / 75, q4 = (i - b*75)*4;
                    *(float4*)&sx[b*SB + q4] = px[it];
                    *(float4*)&sh[b*SB + q4] = ph[it];
                }
            }
            __syncthreads();

            // prefetch next cell in this wavefront (overlaps dot below)
            if (l < lmax) gru_prefetch(l+1, t-1, tid, px, ph);

            // dot products
            {
                const float* wA = sw + (l*18 + tA)*300;
                const float* wB = sw + (l*18 + tB)*300;
                const float* aA = ((tA < 9) ? sx : sh) + lane*SB;
                const float* aB = ((tB < 9) ? sx : sh) + lane*SB;
                unsigned long long accA0 = 0ull, accA1 = 0ull;
                unsigned long long accB0 = 0ull, accB1 = 0ull;
                if (p != 4) {   // shared activation stream
                    #pragma unroll 4
                    for (int kk = 0; kk < 96; kk += 8) {
                        int k = kbeg + kk;
                        ulonglong2 wa0 = *(const ulonglong2*)(wA + k);
                        ulonglong2 wa1 = *(const ulonglong2*)(wA + k + 4);
                        ulonglong2 wb0 = *(const ulonglong2*)(wB + k);
                        ulonglong2 wb1 = *(const ulonglong2*)(wB + k + 4);
                        ulonglong2 x01 = *(const ulonglong2*)(aA + k);
                        ulonglong2 x23 = *(const ulonglong2*)(aA + k + 4);
                        FMA2(accA0, wa0.x, x01.x); FMA2(accA1, wa0.y, x01.y);
                        FMA2(accB0, wb0.x, x01.x); FMA2(accB1, wb0.y, x01.y);
                        FMA2(accA0, wa1.x, x23.x); FMA2(accA1, wa1.y, x23.y);
                        FMA2(accB0, wb1.x, x23.x); FMA2(accB1, wb1.y, x23.y);
                    }
                    {   // tail: 4 floats
                        int k = kbeg + 96;
                        ulonglong2 wa = *(const ulonglong2*)(wA + k);
                        ulonglong2 wb = *(const ulonglong2*)(wB + k);
                        ulonglong2 x01 = *(const ulonglong2*)(aA + k);
                        FMA2(accA0, wa.x, x01.x); FMA2(accA1, wa.y, x01.y);
                        FMA2(accB0, wb.x, x01.x); FMA2(accB1, wb.y, x01.y);
                    }
                } else {        // mixed pair (task 8 reads x, task 9 reads h)
                    #pragma unroll 4
                    for (int kk = 0; kk < 96; kk += 8) {
                        int k = kbeg + kk;
                        ulonglong2 wa0 = *(const ulonglong2*)(wA + k);
                        ulonglong2 wa1 = *(const ulonglong2*)(wA + k + 4);
                        ulonglong2 wb0 = *(const ulonglong2*)(wB + k);
                        ulonglong2 wb1 = *(const ulonglong2*)(wB + k + 4);
                        ulonglong2 x01 = *(const ulonglong2*)(aA + k);
                        ulonglong2 x23 = *(const ulonglong2*)(aA + k + 4);
                        ulonglong2 y01 = *(const ulonglong2*)(aB + k);
                        ulonglong2 y23 = *(const ulonglong2*)(aB + k + 4);
                        FMA2(accA0, wa0.x, x01.x); FMA2(accA1, wa0.y, x01.y);
                        FMA2(accB0, wb0.x, y01.x); FMA2(accB1, wb0.y, y01.y);
                        FMA2(accA0, wa1.x, x23.x); FMA2(accA1, wa1.y, x23.y);
                        FMA2(accB0, wb1.x, y23.x); FMA2(accB1, wb1.y, y23.y);
                    }
                    {
                        int k = kbeg + 96;
                        ulonglong2 wa = *(const ulonglong2*)(wA + k);
                        ulonglong2 wb = *(const ulonglong2*)(wB + k);
                        ulonglong2 x01 = *(const ulonglong2*)(aA + k);
                        ulonglong2 y01 = *(const ulonglong2*)(aB + k);
                        FMA2(accA0, wa.x, x01.x); FMA2(accA1, wa.y, x01.y);
                        FMA2(accB0, wb.x, y01.x); FMA2(accB1, wb.y, y01.y);
                    }
                }
                float a0,a1,a2,a3;
                asm("mov.b64 {%0,%1}, %2;" : "=f"(a0), "=f"(a1) : "l"(accA0));
                asm("mov.b64 {%0,%1}, %2;" : "=f"(a2), "=f"(a3) : "l"(accA1));
                sacc[tA*96 + q*32 + lane] = (a0+a1) + (a2+a3);
                asm("mov.b64 {%0,%1}, %2;" : "=f"(a0), "=f"(a1) : "l"(accB0));
                asm("mov.b64 {%0,%1}, %2;" : "=f"(a2), "=f"(a3) : "l"(accB1));
                sacc[tB*96 + q*32 + lane] = (a0+a1) + (a2+a3);
            }
            __syncthreads();

            // gate combine (hprev from sh — still holds this cell's staging)
            if (tid < 96) {
                int b = tid & 31, jl = tid >> 5;
                int j = j0 + jl;
                #define SAC(tk) (sacc[(tk)*96+b] + sacc[(tk)*96+32+b] + sacc[(tk)*96+64+b])
                float i_r = SAC( 0+jl) + sb[l*18 +      jl];
                float i_z = SAC( 3+jl) + sb[l*18 +  3 + jl];
                float i_n = SAC( 6+jl) + sb[l*18 +  6 + jl];
                float h_r = SAC( 9+jl) + sb[l*18 +  9 + jl];
                float h_z = SAC(12+jl) + sb[l*18 + 12 + jl];
                float h_n = SAC(15+jl) + sb[l*18 + 15 + jl];
                #undef SAC
                float r = 1.f/(1.f + __expf(-(i_r + h_r)));
                float z = 1.f/(1.f + __expf(-(i_z + h_z)));
                float n = tanhf(i_n + r*h_n);
                float hp = sh[b*SB + j];
                float hv = (1.f - z)*n + z*hp;
                g_hall[l][t+1][b][j] = hv;
                if (l == Ld-1) g_cat[(b*Tlen + t)*CATW + 300 + j] = hv;
            }
        }
        grid_barrier();
        if (wf + 1 < Tlen + Ld - 1) {
            int wf2 = wf + 1;
            int l2 = wf2 - (Tlen-1); if (l2 < 0) l2 = 0;
            gru_prefetch(l2, wf2 - l2, tid, px, ph);
        }
    }
}

// ---------------------------------------------------------------------------
// Small GEMM (Q / FEAT only)
// ---------------------------------------------------------------------------
#define MODE_Q    0
#define MODE_FEAT 1
#define TS 68

__global__ void __launch_bounds__(256) gemm_kernel(
        int mode, const float* __restrict__ W, const float* __restrict__ bias,
        int N, int K, int lda) {
    const float* A; float* C;
    if (mode == MODE_Q) { A = g_cat + 300; C = g_q; }
    else                { A = g_cat;       C = g_feat; }

    __shared__ __align__(16) float As[30*TS];
    __shared__ __align__(16) float Bs[30*TS];
    int tid = threadIdx.x;
    int tx = tid & 15, ty = tid >> 4;
    int row0 = blockIdx.y*64, col0 = blockIdx.x*64;

    unsigned long long acc[4][2];
    #pragma unroll
    for (int i = 0; i < 4; i++) { acc[i][0] = 0ull; acc[i][1] = 0ull; }

    for (int k0 = 0; k0 < K; k0 += 30) {
        for (int i = tid; i < 64*30; i += 256) {
            int m = i/30, k = i - m*30;
            As[k*TS + m] = A[(size_t)(row0+m)*lda + k0 + k];
            int col = col0 + m;
            Bs[k*TS + m] = (col < N) ? W[(size_t)col*K + k0 + k] : 0.f;
        }
        __syncthreads();
        #pragma unroll
        for (int k = 0; k < 30; k++) {
            float4 av = *(const float4*)&As[k*TS + ty*4];
            float4 bv = *(const float4*)&Bs[k*TS + tx*4];
            unsigned long long b01, b23;
            asm("mov.b64 %0, {%1,%2};" : "=l"(b01) : "f"(bv.x), "f"(bv.y));
            asm("mov.b64 %0, {%1,%2};" : "=l"(b23) : "f"(bv.z), "f"(bv.w));
            float aarr[4] = {av.x, av.y, av.z, av.w};
            #pragma unroll
            for (int i = 0; i < 4; i++) {
                unsigned long long ap;
                asm("mov.b64 %0, {%1,%1};" : "=l"(ap) : "f"(aarr[i]));
                FMA2(acc[i][0], ap, b01);
                FMA2(acc[i][1], ap, b23);
            }
        }
        __syncthreads();
    }
    #pragma unroll
    for (int i = 0; i < 4; i++) {
        int row = row0 + ty*4 + i;
        float c0,c1,c2,c3;
        asm("mov.b64 {%0,%1}, %2;" : "=f"(c0), "=f"(c1) : "l"(acc[i][0]));
        asm("mov.b64 {%0,%1}, %2;" : "=f"(c2), "=f"(c3) : "l"(acc[i][1]));
        int col = col0 + tx*4;
        float* crow = C + (size_t)row*N;
        if (col+0 < N) crow[col+0] = c0 + bias[col+0];
        if (col+1 < N) crow[col+1] = c1 + bias[col+1];
        if (col+2 < N) crow[col+2] = c2 + bias[col+2];
        if (col+3 < N) crow[col+3] = c3 + bias[col+3];
    }
}

// ---------------------------------------------------------------------------
// OUT GEMM v2: pipelined staging (register prefetch of next K-tile overlaps
// compute). 128x128 tile, 8x8 micro-tile, K-chunk 20, swizzled B layout.
// Epilogue: exp(logit+bias) -> g_logits, row sums -> g_rowsum atomics.
// ---------------------------------------------------------------------------
#define OKC  20
#define ASTR 132
#define BSTR 148
#define OG_ITEMS 640          // 128 rows/cols * 5 float4 per 20-k row

__device__ __forceinline__ void og_prefetch(const float* __restrict__ W,
                                            int k0, int row0, int col0, int tid,
                                            float4* pa, float4* pb) {
    #pragma unroll
    for (int it = 0; it < 3; it++) {
        int i = tid + it*256;
        if (i < OG_ITEMS) {
            int m = i / 5, kq = (i - m*5)*4;
            pa[it] = *(const float4*)(g_feat + (size_t)(row0+m)*300 + k0 + kq);
            int col = col0 + m;
            pb[it] = (col < Vocab) ? *(const float4*)(W + (size_t)col*300 + k0 + kq)
                                   : make_float4(0.f, 0.f, 0.f, 0.f);
        }
    }
}

__global__ void __launch_bounds__(256) out_gemm_kernel(
        const float* __restrict__ W, const float* __restrict__ bias) {
    __shared__ __align__(16) float As[OKC*ASTR];
    __shared__ __align__(16) float Bs[OKC*BSTR];
    const int tid = threadIdx.x;
    const int tx = tid & 15, ty = tid >> 4;
    const int row0 = blockIdx.y*128, col0 = blockIdx.x*128;

    unsigned long long acc[8][4];   // [j][m-pair]
    #pragma unroll
    for (int j = 0; j < 8; j++)
        #pragma unroll
        for (int mp = 0; mp < 4; mp++) acc[j][mp] = 0ull;

    float4 pa[3], pb[3];
    og_prefetch(W, 0, row0, col0, tid, pa, pb);

    for (int kt = 0; kt < 15; kt++) {
        // STS prefetched tile
        #pragma unroll
        for (int it = 0; it < 3; it++) {
            int i = tid + it*256;
            if (i < OG_ITEMS) {
                int m = i / 5, kq = (i - m*5)*4;
                int c = m >> 3, o = m & 7;
                int bbase = 36*(c>>2) + 8*(c&3) + o;
                float va[4] = {pa[it].x, pa[it].y, pa[it].z, pa[it].w};
                float vb[4] = {pb[it].x, pb[it].y, pb[it].z, pb[it].w};
                #pragma unroll
                for (int j = 0; j < 4; j++) {
                    As[(kq+j)*ASTR + m]     = va[j];
                    Bs[(kq+j)*BSTR + bbase] = vb[j];
                }
            }
        }
        __syncthreads();
        if (kt < 14) og_prefetch(W, (kt+1)*OKC, row0, col0, tid, pa, pb);

        #pragma unroll 4
        for (int k = 0; k < OKC; k++) {
            ulonglong2 a01 = *(const ulonglong2*)&As[k*ASTR + ty*8];
            ulonglong2 a23 = *(const ulonglong2*)&As[k*ASTR + ty*8 + 4];
            const float* bb = &Bs[k*BSTR + 36*(tx>>2) + 8*(tx&3)];
            float4 b0 = *(const float4*)bb;
            float4 b1 = *(const float4*)(bb + 4);
            unsigned long long bd[8];
            asm("mov.b64 %0, {%1,%1};" : "=l"(bd[0]) : "f"(b0.x));
            asm("mov.b64 %0, {%1,%1};" : "=l"(bd[1]) : "f"(b0.y));
            asm("mov.b64 %0, {%1,%1};" : "=l"(bd[2]) : "f"(b0.z));
            asm("mov.b64 %0, {%1,%1};" : "=l"(bd[3]) : "f"(b0.w));
            asm("mov.b64 %0, {%1,%1};" : "=l"(bd[4]) : "f"(b1.x));
            asm("mov.b64 %0, {%1,%1};" : "=l"(bd[5]) : "f"(b1.y));
            asm("mov.b64 %0, {%1,%1};" : "=l"(bd[6]) : "f"(b1.z));
            asm("mov.b64 %0, {%1,%1};" : "=l"(bd[7]) : "f"(b1.w));
            #pragma unroll
            for (int j = 0; j < 8; j++) {
                FMA2(acc[j][0], a01.x, bd[j]);
                FMA2(acc[j][1], a01.y, bd[j]);
                FMA2(acc[j][2], a23.x, bd[j]);
                FMA2(acc[j][3], a23.y, bd[j]);
            }
        }
        __syncthreads();
    }

    // epilogue: exp + store + row-sum
    const int cb = col0 + tx*8;
    float bs_[8];
    #pragma unroll
    for (int j = 0; j < 8; j++) bs_[j] = (cb + j < Vocab) ? bias[cb + j] : 0.f;

    #pragma unroll
    for (int mp = 0; mp < 4; mp++) {
        #pragma unroll
        for (int hh = 0; hh < 2; hh++) {
            int r = ty*8 + 2*mp + hh;
            float e[8];
            #pragma unroll
            for (int j = 0; j < 8; j++) {
                float lo, hi;
                asm("mov.b64 {%0,%1}, %2;" : "=f"(lo), "=f"(hi) : "l"(acc[j][mp]));
                float v = hh ? hi : lo;
                e[j] = (cb + j < Vocab) ? __expf(v + bs_[j]) : 0.f;
            }
            float s = e[0]+e[1]+e[2]+e[3]+e[4]+e[5]+e[6]+e[7];
            #pragma unroll
            for (int o = 8; o; o >>= 1) s += __shfl_xor_sync(0xffffffffu, s, o, 16);
            float* crow = g_logits + (size_t)(row0 + r)*Vocab + cb;
            if (cb + 7 < Vocab) {
                *(float4*)crow       = make_float4(e[0], e[1], e[2], e[3]);
                *(float4*)(crow + 4) = make_float4(e[4], e[5], e[6], e[7]);
            } else {
                #pragma unroll
                for (int j = 0; j < 8; j++)
                    if (cb + j < Vocab) crow[j] = e[j];
            }
            if ((tid & 15) == 0) atomicAdd(&g_rowsum[row0 + r], s);
        }
    }
}

// ---------------------------------------------------------------------------
// Attention (unchanged)
// ---------------------------------------------------------------------------
__global__ void __launch_bounds__(256) attn_kernel(
        const float* __restrict__ src, const void* __restrict__ maskp,
        float* __restrict__ attn_out) {
    __shared__ float sq[Hd];
    __shared__ float ss[Slen];
    __shared__ float red[8];
    int row = blockIdx.x;
    int b = row / Tlen;
    int tid = threadIdx.x, lane = tid & 31, warp = tid >> 5;

    for (int h = tid; h < Hd; h += 256) sq[h] = g_q[row*Hd + h];
    __syncthreads();

    const unsigned char* m8  = (const unsigned char*)maskp;
    const int*           m32 = (const int*)maskp;
    int useu8 = g_mask_u8;

    for (int s = warp; s < Slen; s += 8) {
        const float* srow = src + ((size_t)b*Slen + s)*Hd;
        float p = 0.f;
        for (int h = lane; h < Hd; h += 32) p += sq[h]*srow[h];
        #pragma unroll
        for (int o = 16; o; o >>= 1) p += __shfl_xor_sync(0xffffffffu, p, o);
        if (lane == 0) {
            int mk = useu8 ? (int)m8[b*Slen + s] : m32[b*Slen + s];
            ss[s] = mk ? p : -1e9f;
        }
    }
    __syncthreads();

    float mv = -3.4e38f;
    for (int s = tid; s < Slen; s += 256) mv = fmaxf(mv, ss[s]);
    #pragma unroll
    for (int o = 16; o; o >>= 1) mv = fmaxf(mv, __shfl_xor_sync(0xffffffffu, mv, o));
    if (lane == 0) red[warp] = mv;
    __syncthreads();
    if (tid == 0) { float x = red[0]; for (int w = 1; w < 8; w++) x = fmaxf(x, red[w]); red[0] = x; }
    __syncthreads();
    float M = red[0];
    __syncthreads();

    float sv = 0.f;
    for (int s = tid; s < Slen; s += 256) { float e = __expf(ss[s] - M); ss[s] = e; sv += e; }
    #pragma unroll
    for (int o = 16; o; o >>= 1) sv += __shfl_xor_sync(0xffffffffu, sv, o);
    if (lane == 0) red[warp] = sv;
    __syncthreads();
    if (tid == 0) { float x = 0.f; for (int w = 0; w < 8; w++) x += red[w]; red[0] = x; }
    __syncthreads();
    float inv = 1.f / red[0];

    for (int s = tid; s < Slen; s += 256)
        attn_out[(size_t)row*Slen + s] = ss[s]*inv;

    for (int h = tid; h < Hd; h += 256) {
        float a0=0.f, a1=0.f, a2=0.f, a3=0.f;
        const float* sp = src + (size_t)b*Slen*Hd + h;
        for (int s = 0; s < Slen; s += 4) {
            a0 += ss[s  ]*sp[(size_t)(s  )*Hd];
            a1 += ss[s+1]*sp[(size_t)(s+1)*Hd];
            a2 += ss[s+2]*sp[(size_t)(s+2)*Hd];
            a3 += ss[s+3]*sp[(size_t)(s+3)*Hd];
        }
        g_cat[row*CATW + h] = (a0+a1+a2+a3)*inv;
    }
}

// ---------------------------------------------------------------------------
// p_gen (unchanged)
// ---------------------------------------------------------------------------
__global__ void pgen_kernel(const float* __restrict__ pW,
                            const float* __restrict__ pb) {
    int wg = blockIdx.x*(blockDim.x >> 5) + (threadIdx.x >> 5);
    if (wg >= ROWS) return;
    int lane = threadIdx.x & 31;
    const float* crow = g_cat + wg*CATW;
    float a0 = 0.f, a1 = 0.f;
    for (int k = lane; k < CATW; k += 32) {
        float v = crow[k];
        a0 += v*pW[k];
        a1 += v*pW[CATW + k];
    }
    #pragma unroll
    for (int o = 16; o; o >>= 1) {
        a0 += __shfl_xor_sync(0xffffffffu, a0, o);
        a1 += __shfl_xor_sync(0xffffffffu, a1, o);
    }
    if (lane == 0) {
        float l0 = a0 + pb[0], l1 = a1 + pb[1];
        float m = fmaxf(l0, l1);
        float e0 = __expf(l0 - m), e1 = __expf(l1 - m);
        float inv = 1.f/(e0 + e1);
        g_pgen[wg*2+0] = e0*inv;
        g_pgen[wg*2+1] = e1*inv;
    }
}

// ---------------------------------------------------------------------------
// Merged final scale + copy scatter. One block per (b,t) row.
// ---------------------------------------------------------------------------
__global__ void __launch_bounds__(256) scale_scatter_kernel(
        float* __restrict__ out, const int* __restrict__ src_oov,
        const float* __restrict__ attn) {
    int row = blockIdx.x;
    int b = row / Tlen;
    float scale = g_pgen[row*2] / g_rowsum[row];
    const float* lrow = g_logits + (size_t)row*Vocab;
    float* orow = out + (size_t)row*VO;
    for (int v = threadIdx.x; v < VO; v += 256)
        orow[v] = (v < Vocab) ? scale*lrow[v] : 0.f;
    __syncthreads();
    float p1 = g_pgen[row*2+1];
    for (int s = threadIdx.x; s < Slen; s += 256) {
        float a = attn[(size_t)row*Slen + s] * p1;
        int col = src_oov[b*Slen + s];
        atomicAdd(&orow[col], a);
    }
}

// ---------------------------------------------------------------------------
// Host launcher
// ---------------------------------------------------------------------------
extern "C" void kernel_launch(void* const* d_in, const int* in_sizes, int n_in,
                              void* d_out, int out_size) {
    int idx = 0;
    const int*   tokens  = (const int*)  d_in[idx++];
    const float* src     = (const float*)d_in[idx++];
    const void*  mask    =               d_in[idx++];
    const float* hidden0 = (const float*)d_in[idx++];
    const int*   src_oov = (const int*)  d_in[idx++];
    if (idx < n_in && in_sizes[idx] == 1) idx++;   // max_num_oov scalar
    const float* embed   = (const float*)d_in[idx++];
    const float* W_ih    = (const float*)d_in[idx++];
    const float* W_hh    = (const float*)d_in[idx++];
    const float* b_ih    = (const float*)d_in[idx++];
    const float* b_hh    = (const float*)d_in[idx++];
    const float* attn_W  = (const float*)d_in[idx++];
    const float* attn_b  = (const float*)d_in[idx++];
    const float* fc_W    = (const float*)d_in[idx++];
    const float* fc_b    = (const float*)d_in[idx++];
    const float* out_W   = (const float*)d_in[idx++];
    const float* out_b   = (const float*)d_in[idx++];
    const float* pgen_W  = (const float*)d_in[idx++];
    const float* pgen_b  = (const float*)d_in[idx++];

    float* out = (float*)d_out;
    float* attn_out;
    if (out_size >= (int)((size_t)ROWS*VO + (size_t)ROWS*Slen)) {
        attn_out = out + (size_t)ROWS*VO;
    } else {
        void* p = nullptr;
        cudaGetSymbolAddress(&p, g_attn_fallback);
        attn_out = (float*)p;
    }

    cudaFuncSetAttribute(gru_persistent_kernel,
                         cudaFuncAttributeMaxDynamicSharedMemorySize, SMEM_BYTES);

    detect_mask_kernel<<<1,1>>>((const unsigned char*)mask);
    init_hall_kernel<<<(Ld*Bsz*Hd+255)/256,256>>>(hidden0);
    embed_kernel<<<(ROWS*Ed+255)/256,256>>>(tokens, embed);

    gru_persistent_kernel<<<NBLK, NTHR, SMEM_BYTES>>>(W_ih, W_hh, b_ih, b_hh);

    gemm_kernel<<<dim3(5,8),256>>>(MODE_Q, attn_W, attn_b, Hd, Hd, CATW);
    attn_kernel<<<ROWS,256>>>(src, mask, attn_out);
    gemm_kernel<<<dim3(5,8),256>>>(MODE_FEAT, fc_W, fc_b, Hd, 2*Hd, CATW);
    out_gemm_kernel<<<dim3((Vocab+127)/128, 4),256>>>(out_W, out_b);
    pgen_kernel<<<64,256>>>(pgen_W, pgen_b);
    scale_scatter_kernel<<<ROWS,256>>>(out, src_oov, attn_out);
}

// round 14
// speedup vs baseline: 3.0414x; 1.1695x over previous
#include <cuda_runtime.h>
#include <cuda_bf16.h>
#include <math.h>

// ---------------------------------------------------------------------------
// Problem constants
// ---------------------------------------------------------------------------
#define Bsz   32
#define Tlen  16
#define Slen  400
#define Hd    300
#define Ed    300
#define Ld    3
#define Vocab 50000
#define OOV   20
#define ROWS  (Bsz*Tlen)      // 512
#define VO    (Vocab+OOV)     // 50020
#define CATW  900             // [contexts(300) | hiddens(300) | x(300)]

// Persistent GRU config
#define NBLK  100
#define NTHR  864
#define NJ    3
#define SB    308

// GRU smem layout (floats)
#define SW_FLOATS   16200
#define SX_OFF      16200
#define SH_OFF      (SX_OFF + Bsz*SB)
#define SACC_OFF    (SH_OFF + Bsz*SB)
#define SBIAS_OFF   (SACC_OFF + 18*96)
#define SMEM_FLOATS (SBIAS_OFF + 54)
#define SMEM_BYTES  (SMEM_FLOATS*4)

#define FMA2(acc, x, y) asm("fma.rn.f32x2 %0, %1, %2, %0;" : "+l"(acc) : "l"(x), "l"(y))

// MMA out-GEMM config (split-bf16 via mma.sync — arch-generic HMMA path)
#define KP     320            // K padded: 10 chunks of 32 (300 real + 20 zero)
#define BROWS  50048          // vocab padded to 391*128
#define SA     40             // smem tile stride in bf16 (16B-aligned rows, conflict-free frags)

#define MMA_BF16(c, a, b) \
    asm volatile("mma.sync.aligned.m16n8k16.row.col.f32.bf16.bf16.f32 " \
        "{%0,%1,%2,%3}, {%4,%5,%6,%7}, {%8,%9}, {%0,%1,%2,%3};" \
        : "+f"((c)[0]), "+f"((c)[1]), "+f"((c)[2]), "+f"((c)[3]) \
        : "r"((a)[0]), "r"((a)[1]), "r"((a)[2]), "r"((a)[3]), \
          "r"((b)[0]), "r"((b)[1]))

// ---------------------------------------------------------------------------
// Scratch
// ---------------------------------------------------------------------------
__device__ float g_cat[ROWS*CATW];
__device__ float g_hall[Ld][Tlen+1][Bsz][Hd];
__device__ float g_q[ROWS*Hd];
__device__ float g_feat[ROWS*Hd];
__device__ float g_logits[(size_t)ROWS*Vocab];     // exp(logit) after out-GEMM
__device__ float g_rowsum[ROWS];
__device__ float g_pgen[ROWS*2];
__device__ float g_attn_fallback[ROWS*Slen];
__device__ int   g_mask_u8;
// split-bf16 operands for the MMA out-GEMM
__device__ __nv_bfloat16 g_Ah[ROWS*KP];
__device__ __nv_bfloat16 g_Al[ROWS*KP];
__device__ __nv_bfloat16 g_Bh[(size_t)BROWS*KP];
__device__ __nv_bfloat16 g_Bl[(size_t)BROWS*KP];

__device__ unsigned g_bar_cnt = 0;
__device__ unsigned g_bar_gen = 0;

// ---------------------------------------------------------------------------
__global__ void detect_mask_kernel(const unsigned char* __restrict__ m) {
    g_mask_u8 = (m[1] | m[2] | m[3]) ? 1 : 0;
}

__global__ void init_hall_kernel(const float* __restrict__ h0) {
    int i = blockIdx.x*blockDim.x + threadIdx.x;
    if (i < Ld*Bsz*Hd) {
        int l = i / (Bsz*Hd), r = i - l*(Bsz*Hd);
        (&g_hall[l][0][0][0])[r] = h0[i];
    }
    if (i < ROWS) g_rowsum[i] = 0.f;
}

__global__ void embed_kernel(const int* __restrict__ tokens,
                             const float* __restrict__ embed) {
    int i = blockIdx.x*blockDim.x + threadIdx.x;
    if (i < ROWS*Ed) {
        int row = i / Ed, e = i - row*Ed;
        g_cat[row*CATW + 600 + e] = embed[(size_t)tokens[row]*Ed + e];
    }
}

// ---------------------------------------------------------------------------
// Grid barrier
// ---------------------------------------------------------------------------
__device__ __forceinline__ void grid_barrier() {
    __threadfence();
    __syncthreads();
    if (threadIdx.x == 0) {
        unsigned gen = *(volatile unsigned*)&g_bar_gen;
        if (atomicAdd(&g_bar_cnt, 1u) == NBLK - 1u) {
            atomicExch(&g_bar_cnt, 0u);
            __threadfence();
            atomicAdd(&g_bar_gen, 1u);
        } else {
            while (*(volatile unsigned*)&g_bar_gen == gen) __nanosleep(32);
        }
        __threadfence();
    }
    __syncthreads();
}

// ---------------------------------------------------------------------------
// GRU activation prefetch (registers)
// ---------------------------------------------------------------------------
__device__ __forceinline__ void gru_prefetch(int l, int t, int tid,
                                             float4* px, float4* ph) {
    const float* xsrc; size_t xstr;
    if (l == 0) { xsrc = g_cat + t*CATW + 600; xstr = Tlen*CATW; }
    else        { xsrc = &g_hall[l-1][t+1][0][0]; xstr = Hd; }
    const float* hsrc = &g_hall[l][t][0][0];
    #pragma unroll
    for (int it = 0; it < 3; it++) {
        int i = tid + it*NTHR;
        if (i < Bsz*75) {
            int b = i / 75, q4 = (i - b*75)*4;
            px[it] = *(const float4*)(xsrc + (size_t)b*xstr + q4);
            ph[it] = *(const float4*)(hsrc + b*Hd + q4);
        }
    }
}

// ---------------------------------------------------------------------------
// Persistent GRU v5.1 (unchanged from R12 passing build)
// ---------------------------------------------------------------------------
extern __shared__ float s_dyn[];

__global__ void __launch_bounds__(NTHR) gru_persistent_kernel(
        const float* __restrict__ W_ih, const float* __restrict__ W_hh,
        const float* __restrict__ b_ih, const float* __restrict__ b_hh) {
    float* sw   = s_dyn;
    float* sx   = s_dyn + SX_OFF;
    float* sh   = s_dyn + SH_OFF;
    float* sacc = s_dyn + SACC_OFF;
    float* sb   = s_dyn + SBIAS_OFF;

    const int tid  = threadIdx.x;
    const int j0   = blockIdx.x * NJ;
    const int lane = tid & 31, w = tid >> 5;
    const int p = w / 3, q = w - 3*p;
    const int tA = 2*p, tB = tA + 1;
    const int kbeg = q * 100;

    for (int idx = tid; idx < SW_FLOATS; idx += NTHR) {
        int l = idx / 5400, r = idx - l*5400;
        int task = r / 300, k = r - task*300;
        int m = task / 9, t2 = task - m*9;
        int g = t2 / 3, jl = t2 - g*3;
        int row = g*300 + j0 + jl;
        const float* src = (m == 0) ? W_ih : W_hh;
        sw[idx] = src[(size_t)l*270000 + (size_t)row*300 + k];
    }
    if (tid < 54) {
        int l = tid / 18, r = tid % 18;
        int m = r / 9, r2 = r % 9;
        int g = r2 / 3, jl = r2 % 3;
        const float* src = m ? b_hh : b_ih;
        sb[tid] = src[l*900 + g*300 + j0 + jl];
    }

    float4 px[3], ph[3];
    gru_prefetch(0, 0, tid, px, ph);

    for (int wf = 0; wf < Tlen + Ld - 1; wf++) {
        int lmin = wf - (Tlen-1); if (lmin < 0) lmin = 0;
        int lmax = (wf < Ld-1) ? wf : Ld-1;
        for (int l = lmin; l <= lmax; l++) {
            int t = wf - l;

            if (l != lmin) __syncthreads();

            #pragma unroll
            for (int it = 0; it < 3; it++) {
                int i = tid + it*NTHR;
                if (i < Bsz*75) {
                    int b = i / 75, q4 = (i - b*75)*4;
                    *(float4*)&sx[b*SB + q4] = px[it];
                    *(float4*)&sh[b*SB + q4] = ph[it];
                }
            }
            __syncthreads();

            if (l < lmax) gru_prefetch(l+1, t-1, tid, px, ph);

            {
                const float* wA = sw + (l*18 + tA)*300;
                const float* wB = sw + (l*18 + tB)*300;
                const float* aA = ((tA < 9) ? sx : sh) + lane*SB;
                const float* aB = ((tB < 9) ? sx : sh) + lane*SB;
                unsigned long long accA0 = 0ull, accA1 = 0ull;
                unsigned long long accB0 = 0ull, accB1 = 0ull;
                if (p != 4) {
                    #pragma unroll 4
                    for (int kk = 0; kk < 96; kk += 8) {
                        int k = kbeg + kk;
                        ulonglong2 wa0 = *(const ulonglong2*)(wA + k);
                        ulonglong2 wa1 = *(const ulonglong2*)(wA + k + 4);
                        ulonglong2 wb0 = *(const ulonglong2*)(wB + k);
                        ulonglong2 wb1 = *(const ulonglong2*)(wB + k + 4);
                        ulonglong2 x01 = *(const ulonglong2*)(aA + k);
                        ulonglong2 x23 = *(const ulonglong2*)(aA + k + 4);
                        FMA2(accA0, wa0.x, x01.x); FMA2(accA1, wa0.y, x01.y);
                        FMA2(accB0, wb0.x, x01.x); FMA2(accB1, wb0.y, x01.y);
                        FMA2(accA0, wa1.x, x23.x); FMA2(accA1, wa1.y, x23.y);
                        FMA2(accB0, wb1.x, x23.x); FMA2(accB1, wb1.y, x23.y);
                    }
                    {
                        int k = kbeg + 96;
                        ulonglong2 wa = *(const ulonglong2*)(wA + k);
                        ulonglong2 wb = *(const ulonglong2*)(wB + k);
                        ulonglong2 x01 = *(const ulonglong2*)(aA + k);
                        FMA2(accA0, wa.x, x01.x); FMA2(accA1, wa.y, x01.y);
                        FMA2(accB0, wb.x, x01.x); FMA2(accB1, wb.y, x01.y);
                    }
                } else {
                    #pragma unroll 4
                    for (int kk = 0; kk < 96; kk += 8) {
                        int k = kbeg + kk;
                        ulonglong2 wa0 = *(const ulonglong2*)(wA + k);
                        ulonglong2 wa1 = *(const ulonglong2*)(wA + k + 4);
                        ulonglong2 wb0 = *(const ulonglong2*)(wB + k);
                        ulonglong2 wb1 = *(const ulonglong2*)(wB + k + 4);
                        ulonglong2 x01 = *(const ulonglong2*)(aA + k);
                        ulonglong2 x23 = *(const ulonglong2*)(aA + k + 4);
                        ulonglong2 y01 = *(const ulonglong2*)(aB + k);
                        ulonglong2 y23 = *(const ulonglong2*)(aB + k + 4);
                        FMA2(accA0, wa0.x, x01.x); FMA2(accA1, wa0.y, x01.y);
                        FMA2(accB0, wb0.x, y01.x); FMA2(accB1, wb0.y, y01.y);
                        FMA2(accA0, wa1.x, x23.x); FMA2(accA1, wa1.y, x23.y);
                        FMA2(accB0, wb1.x, y23.x); FMA2(accB1, wb1.y, y23.y);
                    }
                    {
                        int k = kbeg + 96;
                        ulonglong2 wa = *(const ulonglong2*)(wA + k);
                        ulonglong2 wb = *(const ulonglong2*)(wB + k);
                        ulonglong2 x01 = *(const ulonglong2*)(aA + k);
                        ulonglong2 y01 = *(const ulonglong2*)(aB + k);
                        FMA2(accA0, wa.x, x01.x); FMA2(accA1, wa.y, x01.y);
                        FMA2(accB0, wb.x, y01.x); FMA2(accB1, wb.y, y01.y);
                    }
                }
                float a0,a1,a2,a3;
                asm("mov.b64 {%0,%1}, %2;" : "=f"(a0), "=f"(a1) : "l"(accA0));
                asm("mov.b64 {%0,%1}, %2;" : "=f"(a2), "=f"(a3) : "l"(accA1));
                sacc[tA*96 + q*32 + lane] = (a0+a1) + (a2+a3);
                asm("mov.b64 {%0,%1}, %2;" : "=f"(a0), "=f"(a1) : "l"(accB0));
                asm("mov.b64 {%0,%1}, %2;" : "=f"(a2), "=f"(a3) : "l"(accB1));
                sacc[tB*96 + q*32 + lane] = (a0+a1) + (a2+a3);
            }
            __syncthreads();

            if (tid < 96) {
                int b = tid & 31, jl = tid >> 5;
                int j = j0 + jl;
                #define SAC(tk) (sacc[(tk)*96+b] + sacc[(tk)*96+32+b] + sacc[(tk)*96+64+b])
                float i_r = SAC( 0+jl) + sb[l*18 +      jl];
                float i_z = SAC( 3+jl) + sb[l*18 +  3 + jl];
                float i_n = SAC( 6+jl) + sb[l*18 +  6 + jl];
                float h_r = SAC( 9+jl) + sb[l*18 +  9 + jl];
                float h_z = SAC(12+jl) + sb[l*18 + 12 + jl];
                float h_n = SAC(15+jl) + sb[l*18 + 15 + jl];
                #undef SAC
                float r = 1.f/(1.f + __expf(-(i_r + h_r)));
                float z = 1.f/(1.f + __expf(-(i_z + h_z)));
                float n = tanhf(i_n + r*h_n);
                float hp = sh[b*SB + j];
                float hv = (1.f - z)*n + z*hp;
                g_hall[l][t+1][b][j] = hv;
                if (l == Ld-1) g_cat[(b*Tlen + t)*CATW + 300 + j] = hv;
            }
        }
        grid_barrier();
        if (wf + 1 < Tlen + Ld - 1) {
            int wf2 = wf + 1;
            int l2 = wf2 - (Tlen-1); if (l2 < 0) l2 = 0;
            gru_prefetch(l2, wf2 - l2, tid, px, ph);
        }
    }
}

// ---------------------------------------------------------------------------
// Small GEMM (Q / FEAT only) — unchanged
// ---------------------------------------------------------------------------
#define MODE_Q    0
#define MODE_FEAT 1
#define TS 68

__global__ void __launch_bounds__(256) gemm_kernel(
        int mode, const float* __restrict__ W, const float* __restrict__ bias,
        int N, int K, int lda) {
    const float* A; float* C;
    if (mode == MODE_Q) { A = g_cat + 300; C = g_q; }
    else                { A = g_cat;       C = g_feat; }

    __shared__ __align__(16) float As[30*TS];
    __shared__ __align__(16) float Bs[30*TS];
    int tid = threadIdx.x;
    int tx = tid & 15, ty = tid >> 4;
    int row0 = blockIdx.y*64, col0 = blockIdx.x*64;

    unsigned long long acc[4][2];
    #pragma unroll
    for (int i = 0; i < 4; i++) { acc[i][0] = 0ull; acc[i][1] = 0ull; }

    for (int k0 = 0; k0 < K; k0 += 30) {
        for (int i = tid; i < 64*30; i += 256) {
            int m = i/30, k = i - m*30;
            As[k*TS + m] = A[(size_t)(row0+m)*lda + k0 + k];
            int col = col0 + m;
            Bs[k*TS + m] = (col < N) ? W[(size_t)col*K + k0 + k] : 0.f;
        }
        __syncthreads();
        #pragma unroll
        for (int k = 0; k < 30; k++) {
            float4 av = *(const float4*)&As[k*TS + ty*4];
            float4 bv = *(const float4*)&Bs[k*TS + tx*4];
            unsigned long long b01, b23;
            asm("mov.b64 %0, {%1,%2};" : "=l"(b01) : "f"(bv.x), "f"(bv.y));
            asm("mov.b64 %0, {%1,%2};" : "=l"(b23) : "f"(bv.z), "f"(bv.w));
            float aarr[4] = {av.x, av.y, av.z, av.w};
            #pragma unroll
            for (int i = 0; i < 4; i++) {
                unsigned long long ap;
                asm("mov.b64 %0, {%1,%1};" : "=l"(ap) : "f"(aarr[i]));
                FMA2(acc[i][0], ap, b01);
                FMA2(acc[i][1], ap, b23);
            }
        }
        __syncthreads();
    }
    #pragma unroll
    for (int i = 0; i < 4; i++) {
        int row = row0 + ty*4 + i;
        float c0,c1,c2,c3;
        asm("mov.b64 {%0,%1}, %2;" : "=f"(c0), "=f"(c1) : "l"(acc[i][0]));
        asm("mov.b64 {%0,%1}, %2;" : "=f"(c2), "=f"(c3) : "l"(acc[i][1]));
        int col = col0 + tx*4;
        float* crow = C + (size_t)row*N;
        if (col+0 < N) crow[col+0] = c0 + bias[col+0];
        if (col+1 < N) crow[col+1] = c1 + bias[col+1];
        if (col+2 < N) crow[col+2] = c2 + bias[col+2];
        if (col+3 < N) crow[col+3] = c3 + bias[col+3];
    }
}

// ---------------------------------------------------------------------------
// Split-bf16 conversion kernels (hi = bf16(v), lo = bf16(v - hi))
// ---------------------------------------------------------------------------
__global__ void convertA_kernel() {
    int i = blockIdx.x*blockDim.x + threadIdx.x;      // pairs
    if (i >= ROWS*(KP/2)) return;
    int r = i / (KP/2), kp = (i - r*(KP/2))*2;
    float v0 = (kp   < Hd) ? g_feat[r*Hd + kp  ] : 0.f;
    float v1 = (kp+1 < Hd) ? g_feat[r*Hd + kp+1] : 0.f;
    __nv_bfloat16 h0 = __float2bfloat16(v0), h1 = __float2bfloat16(v1);
    __nv_bfloat162 hh; hh.x = h0; hh.y = h1;
    __nv_bfloat162 ll;
    ll.x = __float2bfloat16(v0 - __bfloat162float(h0));
    ll.y = __float2bfloat16(v1 - __bfloat162float(h1));
    *(__nv_bfloat162*)&g_Ah[r*KP + kp] = hh;
    *(__nv_bfloat162*)&g_Al[r*KP + kp] = ll;
}

__global__ void convertB_kernel(const float* __restrict__ W) {
    int i = blockIdx.x*blockDim.x + threadIdx.x;      // pairs
    if (i >= BROWS*(KP/2)) return;
    int r = i / (KP/2), kp = (i - r*(KP/2))*2;
    float v0 = 0.f, v1 = 0.f;
    if (r < Vocab) {
        if (kp   < Hd) v0 = W[(size_t)r*Hd + kp  ];
        if (kp+1 < Hd) v1 = W[(size_t)r*Hd + kp+1];
    }
    __nv_bfloat16 h0 = __float2bfloat16(v0), h1 = __float2bfloat16(v1);
    __nv_bfloat162 hh; hh.x = h0; hh.y = h1;
    __nv_bfloat162 ll;
    ll.x = __float2bfloat16(v0 - __bfloat162float(h0));
    ll.y = __float2bfloat16(v1 - __bfloat162float(h1));
    *(__nv_bfloat162*)&g_Bh[(size_t)r*KP + kp] = hh;
    *(__nv_bfloat162*)&g_Bl[(size_t)r*KP + kp] = ll;
}

// ---------------------------------------------------------------------------
// MMA out-GEMM: logits = feat @ out_W^T via split-bf16 mma.sync (3 products
// into one fp32 accumulator). Grid (4 m-tiles, 391 n-tiles), 256 threads
// (8 warps = 2M x 4N, warp tile 64x32). K-chunks of 32, 2 k16-steps each.
// Epilogue: exp(logit+bias) -> g_logits (float2 stores), quad-reduced row
// sums -> g_rowsum atomics.
// ---------------------------------------------------------------------------
__global__ void __launch_bounds__(256) out_gemm_mma_kernel(
        const float* __restrict__ bias) {
    __shared__ __align__(16) __nv_bfloat16 sAh[128*SA];
    __shared__ __align__(16) __nv_bfloat16 sAl[128*SA];
    __shared__ __align__(16) __nv_bfloat16 sBh[128*SA];
    __shared__ __align__(16) __nv_bfloat16 sBl[128*SA];
    __shared__ float sbias[128];

    const int tid = threadIdx.x;
    const int wid = tid >> 5, lane = tid & 31;
    const int g = lane >> 2, q = lane & 3;
    const int wm = wid & 1, wn = wid >> 1;
    const int row0 = blockIdx.x * 128;
    const int col0 = blockIdx.y * 128;

    if (tid < 128) {
        int c = col0 + tid;
        sbias[tid] = (c < Vocab) ? bias[c] : 0.f;
    }

    float acc[4][4][4];
    #pragma unroll
    for (int mf = 0; mf < 4; mf++)
        #pragma unroll
        for (int nf = 0; nf < 4; nf++)
            #pragma unroll
            for (int e = 0; e < 4; e++) acc[mf][nf][e] = 0.f;

    for (int kt = 0; kt < 10; kt++) {
        int k0 = kt * 32;
        if (kt) __syncthreads();     // drain previous chunk's readers
        // stage 4 tiles [128][32] bf16 at stride SA=40
        for (int i = tid; i < 512; i += 256) {
            int r = i >> 2, c8 = (i & 3) * 8;
            size_t aoff = (size_t)(row0 + r)*KP + k0 + c8;
            size_t boff = (size_t)(col0 + r)*KP + k0 + c8;
            *(uint4*)&sAh[r*SA + c8] = *(const uint4*)(g_Ah + aoff);
            *(uint4*)&sAl[r*SA + c8] = *(const uint4*)(g_Al + aoff);
            *(uint4*)&sBh[r*SA + c8] = *(const uint4*)(g_Bh + boff);
            *(uint4*)&sBl[r*SA + c8] = *(const uint4*)(g_Bl + boff);
        }
        __syncthreads();

        #pragma unroll
        for (int kk = 0; kk < 32; kk += 16) {
            unsigned ah[4][4], al[4][4], bh[4][2], bl[4][2];
            #pragma unroll
            for (int mf = 0; mf < 4; mf++) {
                int base = (wm*64 + mf*16 + g)*SA + kk + 2*q;
                ah[mf][0] = *(const unsigned*)&sAh[base];
                ah[mf][1] = *(const unsigned*)&sAh[base + 8*SA];
                ah[mf][2] = *(const unsigned*)&sAh[base + 8];
                ah[mf][3] = *(const unsigned*)&sAh[base + 8*SA + 8];
                al[mf][0] = *(const unsigned*)&sAl[base];
                al[mf][1] = *(const unsigned*)&sAl[base + 8*SA];
                al[mf][2] = *(const unsigned*)&sAl[base + 8];
                al[mf][3] = *(const unsigned*)&sAl[base + 8*SA + 8];
            }
            #pragma unroll
            for (int nf = 0; nf < 4; nf++) {
                int base = (wn*32 + nf*8 + g)*SA + kk + 2*q;
                bh[nf][0] = *(const unsigned*)&sBh[base];
                bh[nf][1] = *(const unsigned*)&sBh[base + 8];
                bl[nf][0] = *(const unsigned*)&sBl[base];
                bl[nf][1] = *(const unsigned*)&sBl[base + 8];
            }
            #pragma unroll
            for (int mf = 0; mf < 4; mf++)
                #pragma unroll
                for (int nf = 0; nf < 4; nf++) {
                    MMA_BF16(acc[mf][nf], ah[mf], bh[nf]);
                    MMA_BF16(acc[mf][nf], al[mf], bh[nf]);
                    MMA_BF16(acc[mf][nf], ah[mf], bl[nf]);
                }
        }
    }
    __syncthreads();   // sbias readers below vs (nothing) — keeps ordering simple

    // epilogue: exp + store + quad-reduced row sums
    #pragma unroll
    for (int mf = 0; mf < 4; mf++) {
        #pragma unroll
        for (int h = 0; h < 2; h++) {
            int row = row0 + wm*64 + mf*16 + h*8 + g;
            float s = 0.f;
            #pragma unroll
            for (int nf = 0; nf < 4; nf++) {
                int cl = wn*32 + nf*8 + 2*q;
                int col = col0 + cl;
                float e0 = 0.f, e1 = 0.f;
                if (col < Vocab) {
                    e0 = __expf(acc[mf][nf][h*2+0] + sbias[cl]);
                    e1 = __expf(acc[mf][nf][h*2+1] + sbias[cl+1]);
                    *(float2*)&g_logits[(size_t)row*Vocab + col] = make_float2(e0, e1);
                }
                s += e0 + e1;
            }
            s += __shfl_xor_sync(0xffffffffu, s, 1);
            s += __shfl_xor_sync(0xffffffffu, s, 2);
            if (q == 0) atomicAdd(&g_rowsum[row], s);
        }
    }
}

// ---------------------------------------------------------------------------
// Attention (unchanged)
// ---------------------------------------------------------------------------
__global__ void __launch_bounds__(256) attn_kernel(
        const float* __restrict__ src, const void* __restrict__ maskp,
        float* __restrict__ attn_out) {
    __shared__ float sq[Hd];
    __shared__ float ss[Slen];
    __shared__ float red[8];
    int row = blockIdx.x;
    int b = row / Tlen;
    int tid = threadIdx.x, lane = tid & 31, warp = tid >> 5;

    for (int h = tid; h < Hd; h += 256) sq[h] = g_q[row*Hd + h];
    __syncthreads();

    const unsigned char* m8  = (const unsigned char*)maskp;
    const int*           m32 = (const int*)maskp;
    int useu8 = g_mask_u8;

    for (int s = warp; s < Slen; s += 8) {
        const float* srow = src + ((size_t)b*Slen + s)*Hd;
        float p = 0.f;
        for (int h = lane; h < Hd; h += 32) p += sq[h]*srow[h];
        #pragma unroll
        for (int o = 16; o; o >>= 1) p += __shfl_xor_sync(0xffffffffu, p, o);
        if (lane == 0) {
            int mk = useu8 ? (int)m8[b*Slen + s] : m32[b*Slen + s];
            ss[s] = mk ? p : -1e9f;
        }
    }
    __syncthreads();

    float mv = -3.4e38f;
    for (int s = tid; s < Slen; s += 256) mv = fmaxf(mv, ss[s]);
    #pragma unroll
    for (int o = 16; o; o >>= 1) mv = fmaxf(mv, __shfl_xor_sync(0xffffffffu, mv, o));
    if (lane == 0) red[warp] = mv;
    __syncthreads();
    if (tid == 0) { float x = red[0]; for (int w = 1; w < 8; w++) x = fmaxf(x, red[w]); red[0] = x; }
    __syncthreads();
    float M = red[0];
    __syncthreads();

    float sv = 0.f;
    for (int s = tid; s < Slen; s += 256) { float e = __expf(ss[s] - M); ss[s] = e; sv += e; }
    #pragma unroll
    for (int o = 16; o; o >>= 1) sv += __shfl_xor_sync(0xffffffffu, sv, o);
    if (lane == 0) red[warp] = sv;
    __syncthreads();
    if (tid == 0) { float x = 0.f; for (int w = 0; w < 8; w++) x += red[w]; red[0] = x; }
    __syncthreads();
    float inv = 1.f / red[0];

    for (int s = tid; s < Slen; s += 256)
        attn_out[(size_t)row*Slen + s] = ss[s]*inv;

    for (int h = tid; h < Hd; h += 256) {
        float a0=0.f, a1=0.f, a2=0.f, a3=0.f;
        const float* sp = src + (size_t)b*Slen*Hd + h;
        for (int s = 0; s < Slen; s += 4) {
            a0 += ss[s  ]*sp[(size_t)(s  )*Hd];
            a1 += ss[s+1]*sp[(size_t)(s+1)*Hd];
            a2 += ss[s+2]*sp[(size_t)(s+2)*Hd];
            a3 += ss[s+3]*sp[(size_t)(s+3)*Hd];
        }
        g_cat[row*CATW + h] = (a0+a1+a2+a3)*inv;
    }
}

// ---------------------------------------------------------------------------
// p_gen (unchanged)
// ---------------------------------------------------------------------------
__global__ void pgen_kernel(const float* __restrict__ pW,
                            const float* __restrict__ pb) {
    int wg = blockIdx.x*(blockDim.x >> 5) + (threadIdx.x >> 5);
    if (wg >= ROWS) return;
    int lane = threadIdx.x & 31;
    const float* crow = g_cat + wg*CATW;
    float a0 = 0.f, a1 = 0.f;
    for (int k = lane; k < CATW; k += 32) {
        float v = crow[k];
        a0 += v*pW[k];
        a1 += v*pW[CATW + k];
    }
    #pragma unroll
    for (int o = 16; o; o >>= 1) {
        a0 += __shfl_xor_sync(0xffffffffu, a0, o);
        a1 += __shfl_xor_sync(0xffffffffu, a1, o);
    }
    if (lane == 0) {
        float l0 = a0 + pb[0], l1 = a1 + pb[1];
        float m = fmaxf(l0, l1);
        float e0 = __expf(l0 - m), e1 = __expf(l1 - m);
        float inv = 1.f/(e0 + e1);
        g_pgen[wg*2+0] = e0*inv;
        g_pgen[wg*2+1] = e1*inv;
    }
}

// ---------------------------------------------------------------------------
// Merged final scale + copy scatter (unchanged)
// ---------------------------------------------------------------------------
__global__ void __launch_bounds__(256) scale_scatter_kernel(
        float* __restrict__ out, const int* __restrict__ src_oov,
        const float* __restrict__ attn) {
    int row = blockIdx.x;
    int b = row / Tlen;
    float scale = g_pgen[row*2] / g_rowsum[row];
    const float* lrow = g_logits + (size_t)row*Vocab;
    float* orow = out + (size_t)row*VO;
    for (int v = threadIdx.x; v < VO; v += 256)
        orow[v] = (v < Vocab) ? scale*lrow[v] : 0.f;
    __syncthreads();
    float p1 = g_pgen[row*2+1];
    for (int s = threadIdx.x; s < Slen; s += 256) {
        float a = attn[(size_t)row*Slen + s] * p1;
        int col = src_oov[b*Slen + s];
        atomicAdd(&orow[col], a);
    }
}

// ---------------------------------------------------------------------------
// Host launcher
// ---------------------------------------------------------------------------
extern "C" void kernel_launch(void* const* d_in, const int* in_sizes, int n_in,
                              void* d_out, int out_size) {
    int idx = 0;
    const int*   tokens  = (const int*)  d_in[idx++];
    const float* src     = (const float*)d_in[idx++];
    const void*  mask    =               d_in[idx++];
    const float* hidden0 = (const float*)d_in[idx++];
    const int*   src_oov = (const int*)  d_in[idx++];
    if (idx < n_in && in_sizes[idx] == 1) idx++;   // max_num_oov scalar
    const float* embed   = (const float*)d_in[idx++];
    const float* W_ih    = (const float*)d_in[idx++];
    const float* W_hh    = (const float*)d_in[idx++];
    const float* b_ih    = (const float*)d_in[idx++];
    const float* b_hh    = (const float*)d_in[idx++];
    const float* attn_W  = (const float*)d_in[idx++];
    const float* attn_b  = (const float*)d_in[idx++];
    const float* fc_W    = (const float*)d_in[idx++];
    const float* fc_b    = (const float*)d_in[idx++];
    const float* out_W   = (const float*)d_in[idx++];
    const float* out_b   = (const float*)d_in[idx++];
    const float* pgen_W  = (const float*)d_in[idx++];
    const float* pgen_b  = (const float*)d_in[idx++];

    float* out = (float*)d_out;
    float* attn_out;
    if (out_size >= (int)((size_t)ROWS*VO + (size_t)ROWS*Slen)) {
        attn_out = out + (size_t)ROWS*VO;
    } else {
        void* p = nullptr;
        cudaGetSymbolAddress(&p, g_attn_fallback);
        attn_out = (float*)p;
    }

    cudaFuncSetAttribute(gru_persistent_kernel,
                         cudaFuncAttributeMaxDynamicSharedMemorySize, SMEM_BYTES);

    detect_mask_kernel<<<1,1>>>((const unsigned char*)mask);
    init_hall_kernel<<<(Ld*Bsz*Hd+255)/256,256>>>(hidden0);
    embed_kernel<<<(ROWS*Ed+255)/256,256>>>(tokens, embed);

    // B-split conversion is independent of the GRU chain; issue it early.
    convertB_kernel<<<(BROWS*(KP/2)+255)/256,256>>>(out_W);

    gru_persistent_kernel<<<NBLK, NTHR, SMEM_BYTES>>>(W_ih, W_hh, b_ih, b_hh);

    gemm_kernel<<<dim3(5,8),256>>>(MODE_Q, attn_W, attn_b, Hd, Hd, CATW);
    attn_kernel<<<ROWS,256>>>(src, mask, attn_out);
    gemm_kernel<<<dim3(5,8),256>>>(MODE_FEAT, fc_W, fc_b, Hd, 2*Hd, CATW);

    convertA_kernel<<<(ROWS*(KP/2)+255)/256,256>>>();
    out_gemm_mma_kernel<<<dim3(4,391),256>>>(out_b);

    pgen_kernel<<<64,256>>>(pgen_W, pgen_b);
    scale_scatter_kernel<<<ROWS,256>>>(out, src_oov, attn_out);
}